// round 2
// baseline (speedup 1.0000x reference)
#include <cuda_runtime.h>

// Problem constants
#define CB 8
#define CQ 900
#define CD 256
#define CNH 8
#define CDH 32
#define CFF 1024
#define CS 13294          // 100*100 + 50*50 + 25*25 + 13*13
#define CBQ (CB*CQ)       // 7200
#define CBS (CB*CS)       // 106352
#define CNLAYERS 6
#define ATTN_SCALE 0.17677669529663687f   // 1/sqrt(32)

// ------------------------- scratch (device globals) -------------------------
__device__ float g_value[CBS*CD];     // projected value, layer-invariant
__device__ float g_x   [CBQ*CD];      // decoder state
__device__ float g_xpq [CBQ*CD];      // x + query_pos
__device__ float g_qkv [CBQ*3*CD];
__device__ float g_attn[CBQ*CD];
__device__ float g_t2  [CBQ*CD];
__device__ float g_off [CBQ*256];     // sampling offsets
__device__ float g_awl [CBQ*128];     // attention-weight logits
__device__ float g_ms  [CBQ*CD];      // msda gather output
__device__ float g_ffh [CBQ*CFF];     // ffn hidden

// ------------------------- elementwise add -------------------------
__global__ void add_kernel(const float* __restrict__ a, const float* __restrict__ b,
                           float* __restrict__ o, int n) {
    int i = blockIdx.x * blockDim.x + threadIdx.x;
    if (i < n) o[i] = a[i] + b[i];
}

// ------------------------- tiled SGEMM: C = A[M,K] @ W[N,K]^T + bias -------------------------
template<bool RELU>
__global__ void gemm_bias(const float* __restrict__ A, const float* __restrict__ W,
                          const float* __restrict__ bias, float* __restrict__ C,
                          int M, int N, int K) {
    __shared__ float As[64][17];
    __shared__ float Bs[64][17];
    int tid = threadIdx.x;
    int tx = tid & 15, ty = tid >> 4;
    int rowBase = blockIdx.y * 64, colBase = blockIdx.x * 64;
    float acc[4][4] = {};

    int am = tid >> 2;            // 0..63
    int ak = (tid & 3) << 2;      // 0,4,8,12
    int garow = rowBase + am;
    int gbrow = colBase + am;

    for (int kt = 0; kt < K; kt += 16) {
        float4 av = make_float4(0.f, 0.f, 0.f, 0.f);
        float4 bv = make_float4(0.f, 0.f, 0.f, 0.f);
        if (garow < M) av = *reinterpret_cast<const float4*>(A + (size_t)garow * K + kt + ak);
        if (gbrow < N) bv = *reinterpret_cast<const float4*>(W + (size_t)gbrow * K + kt + ak);
        As[am][ak+0] = av.x; As[am][ak+1] = av.y; As[am][ak+2] = av.z; As[am][ak+3] = av.w;
        Bs[am][ak+0] = bv.x; Bs[am][ak+1] = bv.y; Bs[am][ak+2] = bv.z; Bs[am][ak+3] = bv.w;
        __syncthreads();
        #pragma unroll
        for (int kk = 0; kk < 16; kk++) {
            float a[4], bb[4];
            #pragma unroll
            for (int i = 0; i < 4; i++) a[i]  = As[ty*4+i][kk];
            #pragma unroll
            for (int j = 0; j < 4; j++) bb[j] = Bs[tx*4+j][kk];
            #pragma unroll
            for (int i = 0; i < 4; i++)
                #pragma unroll
                for (int j = 0; j < 4; j++)
                    acc[i][j] = fmaf(a[i], bb[j], acc[i][j]);
        }
        __syncthreads();
    }
    #pragma unroll
    for (int i = 0; i < 4; i++) {
        int gr = rowBase + ty*4 + i;
        if (gr >= M) continue;
        #pragma unroll
        for (int j = 0; j < 4; j++) {
            int gc = colBase + tx*4 + j;
            if (gc >= N) continue;
            float v = acc[i][j] + bias[gc];
            if (RELU) v = fmaxf(v, 0.f);
            C[(size_t)gr * N + gc] = v;
        }
    }
}

// ------------------------- MHA: one block per (b, h, q) -------------------------
__global__ void attn_kernel(const float* __restrict__ qkv, float* __restrict__ out) {
    int bid = blockIdx.x;
    int q = bid % CQ;
    int h = (bid / CQ) % CNH;
    int b = bid / (CQ * CNH);
    int t = threadIdx.x;          // 128 threads

    __shared__ float s[CQ];
    __shared__ float qs[CDH];
    __shared__ float red[4];
    __shared__ float part[4][CDH];

    if (t < CDH) qs[t] = qkv[((size_t)(b*CQ + q))*768 + h*CDH + t];
    __syncthreads();

    // pass 1: scores + local max
    float lmax = -1e30f;
    for (int k = t; k < CQ; k += 128) {
        const float* kp = qkv + ((size_t)(b*CQ + k))*768 + CD + h*CDH;
        float d0 = 0.f;
        #pragma unroll
        for (int i = 0; i < CDH; i++) d0 = fmaf(qs[i], kp[i], d0);
        d0 *= ATTN_SCALE;
        s[k] = d0;
        lmax = fmaxf(lmax, d0);
    }
    #pragma unroll
    for (int o = 16; o > 0; o >>= 1) lmax = fmaxf(lmax, __shfl_xor_sync(0xffffffffu, lmax, o));
    if ((t & 31) == 0) red[t >> 5] = lmax;
    __syncthreads();
    float bmax = fmaxf(fmaxf(red[0], red[1]), fmaxf(red[2], red[3]));
    __syncthreads();   // protect red before reuse

    // pass 2: exp + sum
    float lsum = 0.f;
    for (int k = t; k < CQ; k += 128) {
        float e = __expf(s[k] - bmax);
        s[k] = e;
        lsum += e;
    }
    #pragma unroll
    for (int o = 16; o > 0; o >>= 1) lsum += __shfl_xor_sync(0xffffffffu, lsum, o);
    if ((t & 31) == 0) red[t >> 5] = lsum;
    __syncthreads();
    float inv = 1.f / (red[0] + red[1] + red[2] + red[3]);

    // pass 3: O = P @ V, split k over 4 warps, each lane owns one d
    int d = t & 31, c = t >> 5;
    float acc = 0.f;
    for (int k = c; k < CQ; k += 4) {
        acc = fmaf(s[k], qkv[((size_t)(b*CQ + k))*768 + 2*CD + h*CDH + d], acc);
    }
    part[c][d] = acc;
    __syncthreads();
    if (t < CDH) {
        out[((size_t)(b*CQ + q))*CD + h*CDH + t] =
            (part[0][t] + part[1][t] + part[2][t] + part[3][t]) * inv;
    }
}

// ------------------------- fused residual-add + LayerNorm -------------------------
__global__ void add_ln_kernel(const float* __restrict__ a, const float* __restrict__ r,
                              const float* __restrict__ g, const float* __restrict__ be,
                              float* __restrict__ out, float* __restrict__ out2) {
    int row = blockIdx.x, t = threadIdx.x;   // 256 threads, D=256
    size_t idx = (size_t)row * CD + t;
    float v = a[idx] + r[idx];

    __shared__ float red[8];
    __shared__ float stat[2];

    float s = v;
    #pragma unroll
    for (int o = 16; o > 0; o >>= 1) s += __shfl_xor_sync(0xffffffffu, s, o);
    if ((t & 31) == 0) red[t >> 5] = s;
    __syncthreads();
    if (t == 0) {
        float tot = 0.f;
        #pragma unroll
        for (int i = 0; i < 8; i++) tot += red[i];
        stat[0] = tot * (1.f / CD);
    }
    __syncthreads();
    float mu = stat[0];
    float d = v - mu;
    float s2 = d * d;
    #pragma unroll
    for (int o = 16; o > 0; o >>= 1) s2 += __shfl_xor_sync(0xffffffffu, s2, o);
    if ((t & 31) == 0) red[t >> 5] = s2;
    __syncthreads();
    if (t == 0) {
        float tot = 0.f;
        #pragma unroll
        for (int i = 0; i < 8; i++) tot += red[i];
        stat[1] = tot * (1.f / CD);
    }
    __syncthreads();
    float o = d * rsqrtf(stat[1] + 1e-5f) * g[t] + be[t];
    out[idx] = o;
    if (out2) out2[idx] = o;
}

// ------------------------- MSDA gather: one block per (b,q), warp = head -------------------------
__global__ void msda_kernel(const float* __restrict__ value, const float* __restrict__ off,
                            const float* __restrict__ awl, const float* __restrict__ refp,
                            const float* __restrict__ vr, float* __restrict__ out) {
    int bq = blockIdx.x;
    int b = bq / CQ;
    int t = threadIdx.x;          // 256 threads = 8 warps
    int h = t >> 5, lane = t & 31;

    // softmax over 16 attention-weight logits of this head (lanes 0..15)
    float logit = (lane < 16) ? awl[(size_t)bq * 128 + h * 16 + lane] : -1e30f;
    float m = logit;
    #pragma unroll
    for (int o = 8; o > 0; o >>= 1) m = fmaxf(m, __shfl_xor_sync(0xffffffffu, m, o, 16));
    float e = (lane < 16) ? __expf(logit - m) : 0.f;
    float es = e;
    #pragma unroll
    for (int o = 8; o > 0; o >>= 1) es += __shfl_xor_sync(0xffffffffu, es, o, 16);
    float p = e / es;   // valid for lanes 0..15 only (others unused)

    float rx = refp[(size_t)bq * 2 + 0];
    float ry = refp[(size_t)bq * 2 + 1];

    const int   Ws[4] = {100, 50, 25, 13};
    const int   Hs[4] = {100, 50, 25, 13};
    const int   ST[4] = {0, 10000, 12500, 13125};

    const float* voff = value + (size_t)b * CS * CD + h * CDH + lane;
    float acc = 0.f;

    #pragma unroll
    for (int l = 0; l < 4; l++) {
        int W_ = Ws[l], H_ = Hs[l], st = ST[l];
        float vrx = vr[b * 8 + l * 2 + 0];
        float vry = vr[b * 8 + l * 2 + 1];
        float bx = rx * vrx * (float)W_ - 0.5f;
        float by = ry * vry * (float)H_ - 0.5f;
        #pragma unroll
        for (int pp = 0; pp < 4; pp++) {
            size_t oidx = (size_t)bq * 256 + (size_t)(((h * 4 + l) * 4 + pp) * 2);
            float x = bx + off[oidx + 0];
            float y = by + off[oidx + 1];
            float w = __shfl_sync(0xffffffffu, p, l * 4 + pp, 32);
            float x0f = floorf(x), y0f = floorf(y);
            float wx = x - x0f, wy = y - y0f;
            int x0 = (int)x0f, y0 = (int)y0f;

            float gsum = 0.f;
            {
                int xi = x0, yi = y0;
                if (xi >= 0 && xi < W_ && yi >= 0 && yi < H_)
                    gsum = fmaf(voff[(size_t)(st + yi * W_ + xi) * CD], (1.f - wx) * (1.f - wy), gsum);
            }
            {
                int xi = x0 + 1, yi = y0;
                if (xi >= 0 && xi < W_ && yi >= 0 && yi < H_)
                    gsum = fmaf(voff[(size_t)(st + yi * W_ + xi) * CD], wx * (1.f - wy), gsum);
            }
            {
                int xi = x0, yi = y0 + 1;
                if (xi >= 0 && xi < W_ && yi >= 0 && yi < H_)
                    gsum = fmaf(voff[(size_t)(st + yi * W_ + xi) * CD], (1.f - wx) * wy, gsum);
            }
            {
                int xi = x0 + 1, yi = y0 + 1;
                if (xi >= 0 && xi < W_ && yi >= 0 && yi < H_)
                    gsum = fmaf(voff[(size_t)(st + yi * W_ + xi) * CD], wx * wy, gsum);
            }
            acc = fmaf(w, gsum, acc);
        }
    }
    out[(size_t)bq * CD + h * CDH + lane] = acc;
}

// ------------------------- inter_refs: reference_points repeated 6x -------------------------
__global__ void write_refs_kernel(const float* __restrict__ refp, float* __restrict__ out) {
    int i = blockIdx.x * blockDim.x + threadIdx.x;
    const int n = CB * CQ * 2;
    if (i < n) {
        float v = refp[i];
        #pragma unroll
        for (int L = 0; L < CNLAYERS; L++) out[(size_t)L * n + i] = v;
    }
}

// ------------------------- driver -------------------------
extern "C" void kernel_launch(void* const* d_in, const int* in_sizes, int n_in,
                              void* d_out, int out_size) {
    const float* tgt      = (const float*)d_in[0];
    const float* refp     = (const float*)d_in[1];
    const float* memory   = (const float*)d_in[2];
    // d_in[3] spatial_shapes, d_in[4] level_start_index : compile-time constants
    const float* vratios  = (const float*)d_in[5];
    const float* qpos     = (const float*)d_in[6];
    const float* sa_in_w  = (const float*)d_in[7];
    const float* sa_in_b  = (const float*)d_in[8];
    const float* sa_out_w = (const float*)d_in[9];
    const float* sa_out_b = (const float*)d_in[10];
    const float* n1_g     = (const float*)d_in[11];
    const float* n1_b     = (const float*)d_in[12];
    const float* n2_g     = (const float*)d_in[13];
    const float* n2_b     = (const float*)d_in[14];
    const float* n3_g     = (const float*)d_in[15];
    const float* n3_b     = (const float*)d_in[16];
    const float* vp_w     = (const float*)d_in[17];
    const float* vp_b     = (const float*)d_in[18];
    const float* so_w     = (const float*)d_in[19];
    const float* so_b     = (const float*)d_in[20];
    const float* aw_w     = (const float*)d_in[21];
    const float* aw_b     = (const float*)d_in[22];
    const float* op_w     = (const float*)d_in[23];
    const float* op_b     = (const float*)d_in[24];
    const float* ff1_w    = (const float*)d_in[25];
    const float* ff1_b    = (const float*)d_in[26];
    const float* ff2_w    = (const float*)d_in[27];
    const float* ff2_b    = (const float*)d_in[28];

    float *value, *x, *xpq, *qkv, *attn, *t2, *off, *awl, *ms, *ffh;
    cudaGetSymbolAddress((void**)&value, g_value);
    cudaGetSymbolAddress((void**)&x,     g_x);
    cudaGetSymbolAddress((void**)&xpq,   g_xpq);
    cudaGetSymbolAddress((void**)&qkv,   g_qkv);
    cudaGetSymbolAddress((void**)&attn,  g_attn);
    cudaGetSymbolAddress((void**)&t2,    g_t2);
    cudaGetSymbolAddress((void**)&off,   g_off);
    cudaGetSymbolAddress((void**)&awl,   g_awl);
    cudaGetSymbolAddress((void**)&ms,    g_ms);
    cudaGetSymbolAddress((void**)&ffh,   g_ffh);

    float* out = (float*)d_out;

    // state init
    cudaMemcpyAsync(x, tgt, sizeof(float) * CBQ * CD, cudaMemcpyDeviceToDevice, 0);

    // layer-invariant value projection (computed ONCE, not per layer)
    gemm_bias<false><<<dim3(CD/64, (CBS + 63)/64), 256>>>(memory, vp_w, vp_b, value, CBS, CD, CD);

    // inter_refs output (reference_points repeated 6x)
    write_refs_kernel<<<(CB*CQ*2 + 255)/256, 256>>>(refp, out + (size_t)CNLAYERS * CBQ * CD);

    const int MB = (CBQ + 63) / 64;   // 113 row-blocks

    for (int L = 0; L < CNLAYERS; L++) {
        // output = output + query_pos
        add_kernel<<<(CBQ*CD + 255)/256, 256>>>(x, qpos, xpq, CBQ*CD);

        // ---- MHA ----
        gemm_bias<false><<<dim3(768/64, MB), 256>>>(xpq, sa_in_w, sa_in_b, qkv, CBQ, 3*CD, CD);
        attn_kernel<<<CB*CNH*CQ, 128>>>(qkv, attn);
        gemm_bias<false><<<dim3(CD/64, MB), 256>>>(attn, sa_out_w, sa_out_b, t2, CBQ, CD, CD);
        add_ln_kernel<<<CBQ, CD>>>(xpq, t2, n1_g, n1_b, x, nullptr);

        // ---- MSDA ----
        gemm_bias<false><<<dim3(256/64, MB), 256>>>(x, so_w, so_b, off, CBQ, 256, CD);
        gemm_bias<false><<<dim3(128/64, MB), 256>>>(x, aw_w, aw_b, awl, CBQ, 128, CD);
        msda_kernel<<<CBQ, 256>>>(value, off, awl, refp, vratios, ms);
        gemm_bias<false><<<dim3(CD/64, MB), 256>>>(ms, op_w, op_b, t2, CBQ, CD, CD);
        add_ln_kernel<<<CBQ, CD>>>(x, t2, n2_g, n2_b, x, nullptr);

        // ---- FFN ----
        gemm_bias<true ><<<dim3(CFF/64, MB), 256>>>(x, ff1_w, ff1_b, ffh, CBQ, CFF, CD);
        gemm_bias<false><<<dim3(CD/64, MB), 256>>>(ffh, ff2_w, ff2_b, t2, CBQ, CD, CFF);
        add_ln_kernel<<<CBQ, CD>>>(x, t2, n3_g, n3_b, x, out + (size_t)L * CBQ * CD);
    }
}

// round 3
// speedup vs baseline: 6.0576x; 6.0576x over previous
#include <cuda_runtime.h>

// Problem constants
#define CB 8
#define CQ 900
#define CD 256
#define CNH 8
#define CDH 32
#define CFF 1024
#define CS 13294          // 100*100 + 50*50 + 25*25 + 13*13
#define CBQ (CB*CQ)       // 7200
#define CBS (CB*CS)       // 106352
#define CNLAYERS 6
#define ATTN_SCALE 0.17677669529663687f   // 1/sqrt(32)

// ------------------------- scratch (device globals) -------------------------
__device__ float g_value[CBS*CD];     // projected value, layer-invariant
__device__ float g_x   [CBQ*CD];      // decoder state
__device__ float g_xpq [CBQ*CD];      // x + query_pos
__device__ float g_qkv [CBQ*3*CD];
__device__ float g_attn[CBQ*CD];
__device__ float g_t2  [CBQ*CD];
__device__ float g_off [CBQ*256];     // sampling offsets
__device__ float g_awl [CBQ*128];     // attention-weight logits
__device__ float g_ms  [CBQ*CD];      // msda gather output
__device__ float g_ffh [CBQ*CFF];     // ffn hidden

// ------------------------- elementwise add -------------------------
__global__ void add_kernel(const float* __restrict__ a, const float* __restrict__ b,
                           float* __restrict__ o, int n) {
    int i = blockIdx.x * blockDim.x + threadIdx.x;
    if (i < n) o[i] = a[i] + b[i];
}

// ------------------------- tiled SGEMM: C = A[M,K] @ W[N,K]^T + bias -------------------------
template<bool RELU>
__global__ void gemm_bias(const float* __restrict__ A, const float* __restrict__ W,
                          const float* __restrict__ bias, float* __restrict__ C,
                          int M, int N, int K) {
    __shared__ float As[64][17];
    __shared__ float Bs[64][17];
    int tid = threadIdx.x;
    int tx = tid & 15, ty = tid >> 4;
    int rowBase = blockIdx.y * 64, colBase = blockIdx.x * 64;
    float acc[4][4] = {};

    int am = tid >> 2;            // 0..63
    int ak = (tid & 3) << 2;      // 0,4,8,12
    int garow = rowBase + am;
    int gbrow = colBase + am;

    for (int kt = 0; kt < K; kt += 16) {
        float4 av = make_float4(0.f, 0.f, 0.f, 0.f);
        float4 bv = make_float4(0.f, 0.f, 0.f, 0.f);
        if (garow < M) av = *reinterpret_cast<const float4*>(A + (size_t)garow * K + kt + ak);
        if (gbrow < N) bv = *reinterpret_cast<const float4*>(W + (size_t)gbrow * K + kt + ak);
        As[am][ak+0] = av.x; As[am][ak+1] = av.y; As[am][ak+2] = av.z; As[am][ak+3] = av.w;
        Bs[am][ak+0] = bv.x; Bs[am][ak+1] = bv.y; Bs[am][ak+2] = bv.z; Bs[am][ak+3] = bv.w;
        __syncthreads();
        #pragma unroll
        for (int kk = 0; kk < 16; kk++) {
            float a[4], bb[4];
            #pragma unroll
            for (int i = 0; i < 4; i++) a[i]  = As[ty*4+i][kk];
            #pragma unroll
            for (int j = 0; j < 4; j++) bb[j] = Bs[tx*4+j][kk];
            #pragma unroll
            for (int i = 0; i < 4; i++)
                #pragma unroll
                for (int j = 0; j < 4; j++)
                    acc[i][j] = fmaf(a[i], bb[j], acc[i][j]);
        }
        __syncthreads();
    }
    #pragma unroll
    for (int i = 0; i < 4; i++) {
        int gr = rowBase + ty*4 + i;
        if (gr >= M) continue;
        #pragma unroll
        for (int j = 0; j < 4; j++) {
            int gc = colBase + tx*4 + j;
            if (gc >= N) continue;
            float v = acc[i][j] + bias[gc];
            if (RELU) v = fmaxf(v, 0.f);
            C[(size_t)gr * N + gc] = v;
        }
    }
}

// ------------------------- flash attention: block = (qtile, h, b) -------------------------
// 256 threads = 8 warps; warp owns 8 q-rows; lane owns head-dim channel.
__global__ void flash_attn_kernel(const float* __restrict__ qkv, float* __restrict__ out) {
    const int qt = blockIdx.x, h = blockIdx.y, b = blockIdx.z;
    const int t = threadIdx.x, w = t >> 5, lane = t & 31;

    __shared__ float Qs[64][33];
    __shared__ float Ks[64][33];
    __shared__ float Vs[64][33];

    const int q0 = qt * 64;
    const size_t basebq = (size_t)b * CQ;

    // load Q tile (pre-scaled), coalesced 128B rows
    for (int i = t; i < 64 * 32; i += 256) {
        int r = i >> 5, c = i & 31;
        int gq = q0 + r;
        Qs[r][c] = (gq < CQ) ? qkv[(basebq + gq) * 768 + h * CDH + c] * ATTN_SCALE : 0.f;
    }

    float acc[8], mr[8], lr[8];
    #pragma unroll
    for (int i = 0; i < 8; i++) { acc[i] = 0.f; mr[i] = -1e30f; lr[i] = 0.f; }

    for (int k0 = 0; k0 < CQ; k0 += 64) {
        __syncthreads();
        for (int i = t; i < 64 * 32; i += 256) {
            int r = i >> 5, c = i & 31;
            int gk = k0 + r;
            if (gk < CQ) {
                const float* p = qkv + (basebq + gk) * 768 + h * CDH + c;
                Ks[r][c] = p[CD];
                Vs[r][c] = p[2 * CD];
            } else { Ks[r][c] = 0.f; Vs[r][c] = 0.f; }
        }
        __syncthreads();

        // scores: 8 rows x 64 keys per warp (key = lane and lane+32)
        float s0[8], s1[8];
        #pragma unroll
        for (int i = 0; i < 8; i++) { s0[i] = 0.f; s1[i] = 0.f; }
        #pragma unroll
        for (int c = 0; c < 32; c++) {
            float k0v = Ks[lane][c];
            float k1v = Ks[32 + lane][c];
            #pragma unroll
            for (int i = 0; i < 8; i++) {
                float qv = Qs[w * 8 + i][c];
                s0[i] = fmaf(qv, k0v, s0[i]);
                s1[i] = fmaf(qv, k1v, s1[i]);
            }
        }

        #pragma unroll
        for (int u = 0; u < 2; u++) {
            const int kb = k0 + u * 32;
            const bool valid = (kb + lane) < CQ;
            float p[8];
            #pragma unroll
            for (int i = 0; i < 8; i++) {
                float sv = valid ? (u == 0 ? s0[i] : s1[i]) : -1e30f;
                float cm = sv;
                #pragma unroll
                for (int o = 16; o > 0; o >>= 1)
                    cm = fmaxf(cm, __shfl_xor_sync(0xffffffffu, cm, o));
                float nm = fmaxf(mr[i], cm);
                float f  = __expf(mr[i] - nm);
                float pv = __expf(sv - nm);
                float ps = pv;
                #pragma unroll
                for (int o = 16; o > 0; o >>= 1)
                    ps += __shfl_xor_sync(0xffffffffu, ps, o);
                lr[i] = lr[i] * f + ps;
                acc[i] *= f;
                mr[i] = nm;
                p[i] = pv;
            }
            #pragma unroll
            for (int k = 0; k < 32; k++) {
                float vv = Vs[u * 32 + k][lane];
                #pragma unroll
                for (int i = 0; i < 8; i++)
                    acc[i] = fmaf(__shfl_sync(0xffffffffu, p[i], k), vv, acc[i]);
            }
        }
    }

    #pragma unroll
    for (int i = 0; i < 8; i++) {
        int gq = q0 + w * 8 + i;
        if (gq < CQ)
            out[(basebq + gq) * CD + h * CDH + lane] = acc[i] / lr[i];
    }
}

// ------------------------- fused residual-add + LayerNorm -------------------------
__global__ void add_ln_kernel(const float* __restrict__ a, const float* __restrict__ r,
                              const float* __restrict__ g, const float* __restrict__ be,
                              float* __restrict__ out, float* __restrict__ out2) {
    int row = blockIdx.x, t = threadIdx.x;   // 256 threads, D=256
    size_t idx = (size_t)row * CD + t;
    float v = a[idx] + r[idx];

    __shared__ float red[8];
    __shared__ float stat[2];

    float s = v;
    #pragma unroll
    for (int o = 16; o > 0; o >>= 1) s += __shfl_xor_sync(0xffffffffu, s, o);
    if ((t & 31) == 0) red[t >> 5] = s;
    __syncthreads();
    if (t == 0) {
        float tot = 0.f;
        #pragma unroll
        for (int i = 0; i < 8; i++) tot += red[i];
        stat[0] = tot * (1.f / CD);
    }
    __syncthreads();
    float mu = stat[0];
    float d = v - mu;
    float s2 = d * d;
    #pragma unroll
    for (int o = 16; o > 0; o >>= 1) s2 += __shfl_xor_sync(0xffffffffu, s2, o);
    if ((t & 31) == 0) red[t >> 5] = s2;
    __syncthreads();
    if (t == 0) {
        float tot = 0.f;
        #pragma unroll
        for (int i = 0; i < 8; i++) tot += red[i];
        stat[1] = tot * (1.f / CD);
    }
    __syncthreads();
    float o = d * rsqrtf(stat[1] + 1e-5f) * g[t] + be[t];
    out[idx] = o;
    if (out2) out2[idx] = o;
}

// ------------------------- MSDA gather: one block per (b,q), warp = head -------------------------
__global__ void msda_kernel(const float* __restrict__ value, const float* __restrict__ off,
                            const float* __restrict__ awl, const float* __restrict__ refp,
                            const float* __restrict__ vr, float* __restrict__ out) {
    int bq = blockIdx.x;
    int b = bq / CQ;
    int t = threadIdx.x;          // 256 threads = 8 warps
    int h = t >> 5, lane = t & 31;

    // softmax over 16 attention-weight logits of this head (lanes 0..15)
    float logit = (lane < 16) ? awl[(size_t)bq * 128 + h * 16 + lane] : -1e30f;
    float m = logit;
    #pragma unroll
    for (int o = 8; o > 0; o >>= 1) m = fmaxf(m, __shfl_xor_sync(0xffffffffu, m, o, 16));
    float e = (lane < 16) ? __expf(logit - m) : 0.f;
    float es = e;
    #pragma unroll
    for (int o = 8; o > 0; o >>= 1) es += __shfl_xor_sync(0xffffffffu, es, o, 16);
    float p = e / es;   // valid for lanes 0..15 only

    float rx = refp[(size_t)bq * 2 + 0];
    float ry = refp[(size_t)bq * 2 + 1];

    const int   Ws[4] = {100, 50, 25, 13};
    const int   Hs[4] = {100, 50, 25, 13};
    const int   ST[4] = {0, 10000, 12500, 13125};

    const float* voff = value + (size_t)b * CS * CD + h * CDH + lane;
    float acc = 0.f;

    #pragma unroll
    for (int l = 0; l < 4; l++) {
        int W_ = Ws[l], H_ = Hs[l], st = ST[l];
        float vrx = vr[b * 8 + l * 2 + 0];
        float vry = vr[b * 8 + l * 2 + 1];
        float bx = rx * vrx * (float)W_ - 0.5f;
        float by = ry * vry * (float)H_ - 0.5f;
        #pragma unroll
        for (int pp = 0; pp < 4; pp++) {
            size_t oidx = (size_t)bq * 256 + (size_t)(((h * 4 + l) * 4 + pp) * 2);
            float x = bx + off[oidx + 0];
            float y = by + off[oidx + 1];
            float w = __shfl_sync(0xffffffffu, p, l * 4 + pp, 32);
            float x0f = floorf(x), y0f = floorf(y);
            float wx = x - x0f, wy = y - y0f;
            int x0 = (int)x0f, y0 = (int)y0f;

            float gsum = 0.f;
            {
                int xi = x0, yi = y0;
                if (xi >= 0 && xi < W_ && yi >= 0 && yi < H_)
                    gsum = fmaf(voff[(size_t)(st + yi * W_ + xi) * CD], (1.f - wx) * (1.f - wy), gsum);
            }
            {
                int xi = x0 + 1, yi = y0;
                if (xi >= 0 && xi < W_ && yi >= 0 && yi < H_)
                    gsum = fmaf(voff[(size_t)(st + yi * W_ + xi) * CD], wx * (1.f - wy), gsum);
            }
            {
                int xi = x0, yi = y0 + 1;
                if (xi >= 0 && xi < W_ && yi >= 0 && yi < H_)
                    gsum = fmaf(voff[(size_t)(st + yi * W_ + xi) * CD], (1.f - wx) * wy, gsum);
            }
            {
                int xi = x0 + 1, yi = y0 + 1;
                if (xi >= 0 && xi < W_ && yi >= 0 && yi < H_)
                    gsum = fmaf(voff[(size_t)(st + yi * W_ + xi) * CD], wx * wy, gsum);
            }
            acc = fmaf(w, gsum, acc);
        }
    }
    out[(size_t)bq * CD + h * CDH + lane] = acc;
}

// ------------------------- inter_refs: reference_points repeated 6x -------------------------
__global__ void write_refs_kernel(const float* __restrict__ refp, float* __restrict__ out) {
    int i = blockIdx.x * blockDim.x + threadIdx.x;
    const int n = CB * CQ * 2;
    if (i < n) {
        float v = refp[i];
        #pragma unroll
        for (int L = 0; L < CNLAYERS; L++) out[(size_t)L * n + i] = v;
    }
}

// ------------------------- driver -------------------------
extern "C" void kernel_launch(void* const* d_in, const int* in_sizes, int n_in,
                              void* d_out, int out_size) {
    const float* tgt      = (const float*)d_in[0];
    const float* refp     = (const float*)d_in[1];
    const float* memory   = (const float*)d_in[2];
    const float* vratios  = (const float*)d_in[5];
    const float* qpos     = (const float*)d_in[6];
    const float* sa_in_w  = (const float*)d_in[7];
    const float* sa_in_b  = (const float*)d_in[8];
    const float* sa_out_w = (const float*)d_in[9];
    const float* sa_out_b = (const float*)d_in[10];
    const float* n1_g     = (const float*)d_in[11];
    const float* n1_b     = (const float*)d_in[12];
    const float* n2_g     = (const float*)d_in[13];
    const float* n2_b     = (const float*)d_in[14];
    const float* n3_g     = (const float*)d_in[15];
    const float* n3_b     = (const float*)d_in[16];
    const float* vp_w     = (const float*)d_in[17];
    const float* vp_b     = (const float*)d_in[18];
    const float* so_w     = (const float*)d_in[19];
    const float* so_b     = (const float*)d_in[20];
    const float* aw_w     = (const float*)d_in[21];
    const float* aw_b     = (const float*)d_in[22];
    const float* op_w     = (const float*)d_in[23];
    const float* op_b     = (const float*)d_in[24];
    const float* ff1_w    = (const float*)d_in[25];
    const float* ff1_b    = (const float*)d_in[26];
    const float* ff2_w    = (const float*)d_in[27];
    const float* ff2_b    = (const float*)d_in[28];

    float *value, *x, *xpq, *qkv, *attn, *t2, *off, *awl, *ms, *ffh;
    cudaGetSymbolAddress((void**)&value, g_value);
    cudaGetSymbolAddress((void**)&x,     g_x);
    cudaGetSymbolAddress((void**)&xpq,   g_xpq);
    cudaGetSymbolAddress((void**)&qkv,   g_qkv);
    cudaGetSymbolAddress((void**)&attn,  g_attn);
    cudaGetSymbolAddress((void**)&t2,    g_t2);
    cudaGetSymbolAddress((void**)&off,   g_off);
    cudaGetSymbolAddress((void**)&awl,   g_awl);
    cudaGetSymbolAddress((void**)&ms,    g_ms);
    cudaGetSymbolAddress((void**)&ffh,   g_ffh);

    float* out = (float*)d_out;

    // state init
    cudaMemcpyAsync(x, tgt, sizeof(float) * CBQ * CD, cudaMemcpyDeviceToDevice, 0);

    // layer-invariant value projection (computed ONCE, not per layer)
    gemm_bias<false><<<dim3(CD/64, (CBS + 63)/64), 256>>>(memory, vp_w, vp_b, value, CBS, CD, CD);

    // inter_refs output (reference_points repeated 6x)
    write_refs_kernel<<<(CB*CQ*2 + 255)/256, 256>>>(refp, out + (size_t)CNLAYERS * CBQ * CD);

    const int MB = (CBQ + 63) / 64;   // 113 row-blocks

    for (int L = 0; L < CNLAYERS; L++) {
        // output = output + query_pos
        add_kernel<<<(CBQ*CD + 255)/256, 256>>>(x, qpos, xpq, CBQ*CD);

        // ---- MHA ----
        gemm_bias<false><<<dim3(768/64, MB), 256>>>(xpq, sa_in_w, sa_in_b, qkv, CBQ, 3*CD, CD);
        flash_attn_kernel<<<dim3(15, CNH, CB), 256>>>(qkv, attn);
        gemm_bias<false><<<dim3(CD/64, MB), 256>>>(attn, sa_out_w, sa_out_b, t2, CBQ, CD, CD);
        add_ln_kernel<<<CBQ, CD>>>(xpq, t2, n1_g, n1_b, x, nullptr);

        // ---- MSDA ----
        gemm_bias<false><<<dim3(256/64, MB), 256>>>(x, so_w, so_b, off, CBQ, 256, CD);
        gemm_bias<false><<<dim3(128/64, MB), 256>>>(x, aw_w, aw_b, awl, CBQ, 128, CD);
        msda_kernel<<<CBQ, 256>>>(value, off, awl, refp, vratios, ms);
        gemm_bias<false><<<dim3(CD/64, MB), 256>>>(ms, op_w, op_b, t2, CBQ, CD, CD);
        add_ln_kernel<<<CBQ, CD>>>(x, t2, n2_g, n2_b, x, nullptr);

        // ---- FFN ----
        gemm_bias<true ><<<dim3(CFF/64, MB), 256>>>(x, ff1_w, ff1_b, ffh, CBQ, CFF, CD);
        gemm_bias<false><<<dim3(CD/64, MB), 256>>>(ffh, ff2_w, ff2_b, t2, CBQ, CD, CFF);
        add_ln_kernel<<<CBQ, CD>>>(x, t2, n3_g, n3_b, x, out + (size_t)L * CBQ * CD);
    }
}

// round 4
// speedup vs baseline: 6.3244x; 1.0440x over previous
#include <cuda_runtime.h>

// Problem constants
#define CB 8
#define CQ 900
#define CD 256
#define CNH 8
#define CDH 32
#define CFF 1024
#define CS 13294          // 100*100 + 50*50 + 25*25 + 13*13
#define CBQ (CB*CQ)       // 7200
#define CBS (CB*CS)       // 106352
#define CNLAYERS 6
#define ATTN_SCALE 0.17677669529663687f   // 1/sqrt(32)

// ------------------------- scratch (device globals) -------------------------
__device__ float g_value[CBS*CD];     // projected value, layer-invariant
__device__ float g_x   [CBQ*CD];      // decoder state
__device__ float g_xpq [CBQ*CD];      // x + query_pos
__device__ float g_qkv [CBQ*3*CD];
__device__ float g_attn[CBQ*CD];
__device__ float g_t2  [CBQ*CD];
__device__ float g_off [CBQ*256];     // sampling offsets
__device__ float g_awl [CBQ*128];     // attention-weight logits
__device__ float g_ms  [CBQ*CD];      // msda gather output
__device__ float g_ffh [CBQ*CFF];     // ffn hidden

// ------------------------- f32x2 packed helpers -------------------------
__device__ __forceinline__ unsigned long long pack2(float lo, float hi) {
    unsigned long long r;
    asm("mov.b64 %0, {%1, %2};" : "=l"(r) : "f"(lo), "f"(hi));
    return r;
}
__device__ __forceinline__ void fma2(unsigned long long& d, unsigned long long a, unsigned long long b) {
    asm("fma.rn.f32x2 %0, %1, %2, %0;" : "+l"(d) : "l"(a), "l"(b));
}
__device__ __forceinline__ float2 unpack2(unsigned long long v) {
    float2 f;
    asm("mov.b64 {%0, %1}, %2;" : "=f"(f.x), "=f"(f.y) : "l"(v));
    return f;
}

// ------------------------- elementwise add -------------------------
__global__ void add_kernel(const float* __restrict__ a, const float* __restrict__ b,
                           float* __restrict__ o, int n) {
    int i = blockIdx.x * blockDim.x + threadIdx.x;
    if (i < n) o[i] = a[i] + b[i];
}

// ------------------------- 128x128 SGEMM, f32x2 FMA: C = A[M,K] @ W[N,K]^T + bias -------------------------
// Requires: N multiple of 128, K multiple of 16. M arbitrary.
template<bool RELU>
__global__ __launch_bounds__(256)
void gemm128(const float* __restrict__ A, const float* __restrict__ W,
             const float* __restrict__ bias, float* __restrict__ C,
             int M, int N, int K) {
    __shared__ float As[16][132];
    __shared__ float Bs[16][132];

    const int tid  = threadIdx.x;
    const int warp = tid >> 5, lane = tid & 31;
    const int warpM = warp & 3, warpN = warp >> 2;
    const int mBase = warpM * 32 + (lane >> 3) * 8;   // within-tile row of 8-row strip
    const int nBase = warpN * 64 + (lane & 7) * 8;    // within-tile col of 8-col strip
    const int rowBase = blockIdx.y * 128, colBase = blockIdx.x * 128;

    // loader mapping: each thread loads 4 float4 per K-tile (2 A rows, 2 B rows)
    const int lm = tid >> 2;            // 0..63
    const int lk = (tid & 3) << 2;      // 0,4,8,12

    const int r0 = rowBase + lm, r1 = rowBase + lm + 64;
    const float* pa0 = A + (size_t)r0 * K + lk;
    const float* pa1 = A + (size_t)r1 * K + lk;
    const float* pb0 = W + (size_t)(colBase + lm) * K + lk;
    const float* pb1 = W + (size_t)(colBase + lm + 64) * K + lk;
    const bool v0 = r0 < M, v1 = r1 < M;

    unsigned long long acc[8][4];
    #pragma unroll
    for (int i = 0; i < 8; i++)
        #pragma unroll
        for (int j = 0; j < 4; j++) acc[i][j] = 0ull;

    const float4 fz = make_float4(0.f, 0.f, 0.f, 0.f);
    float4 ra0 = v0 ? *(const float4*)pa0 : fz;
    float4 ra1 = v1 ? *(const float4*)pa1 : fz;
    float4 rb0 = *(const float4*)pb0;
    float4 rb1 = *(const float4*)pb1;

    const int ntiles = K >> 4;
    for (int kt = 0; kt < ntiles; kt++) {
        // stage registers -> smem (transpose to K-major)
        As[lk+0][lm]    = ra0.x; As[lk+1][lm]    = ra0.y; As[lk+2][lm]    = ra0.z; As[lk+3][lm]    = ra0.w;
        As[lk+0][lm+64] = ra1.x; As[lk+1][lm+64] = ra1.y; As[lk+2][lm+64] = ra1.z; As[lk+3][lm+64] = ra1.w;
        Bs[lk+0][lm]    = rb0.x; Bs[lk+1][lm]    = rb0.y; Bs[lk+2][lm]    = rb0.z; Bs[lk+3][lm]    = rb0.w;
        Bs[lk+0][lm+64] = rb1.x; Bs[lk+1][lm+64] = rb1.y; Bs[lk+2][lm+64] = rb1.z; Bs[lk+3][lm+64] = rb1.w;
        __syncthreads();

        // prefetch next K-tile into registers (overlaps with compute below)
        if (kt + 1 < ntiles) {
            const int off = (kt + 1) << 4;
            ra0 = v0 ? *(const float4*)(pa0 + off) : fz;
            ra1 = v1 ? *(const float4*)(pa1 + off) : fz;
            rb0 = *(const float4*)(pb0 + off);
            rb1 = *(const float4*)(pb1 + off);
        }

        #pragma unroll
        for (int kk = 0; kk < 16; kk++) {
            float4 aA = *(const float4*)&As[kk][mBase];
            float4 aB = *(const float4*)&As[kk][mBase + 4];
            float4 b0 = *(const float4*)&Bs[kk][nBase];
            float4 b1 = *(const float4*)&Bs[kk][nBase + 4];
            unsigned long long bp0 = pack2(b0.x, b0.y);
            unsigned long long bp1 = pack2(b0.z, b0.w);
            unsigned long long bp2 = pack2(b1.x, b1.y);
            unsigned long long bp3 = pack2(b1.z, b1.w);
            float av[8] = {aA.x, aA.y, aA.z, aA.w, aB.x, aB.y, aB.z, aB.w};
            #pragma unroll
            for (int i = 0; i < 8; i++) {
                unsigned long long ad = pack2(av[i], av[i]);
                fma2(acc[i][0], ad, bp0);
                fma2(acc[i][1], ad, bp1);
                fma2(acc[i][2], ad, bp2);
                fma2(acc[i][3], ad, bp3);
            }
        }
        __syncthreads();
    }

    // epilogue
    const int gcol = colBase + nBase;
    float4 bv0 = *(const float4*)&bias[gcol];
    float4 bv1 = *(const float4*)&bias[gcol + 4];
    #pragma unroll
    for (int i = 0; i < 8; i++) {
        int gm = rowBase + mBase + i;
        if (gm >= M) break;
        float2 c0 = unpack2(acc[i][0]);
        float2 c1 = unpack2(acc[i][1]);
        float2 c2 = unpack2(acc[i][2]);
        float2 c3 = unpack2(acc[i][3]);
        float4 o0 = make_float4(c0.x + bv0.x, c0.y + bv0.y, c1.x + bv0.z, c1.y + bv0.w);
        float4 o1 = make_float4(c2.x + bv1.x, c2.y + bv1.y, c3.x + bv1.z, c3.y + bv1.w);
        if (RELU) {
            o0.x = fmaxf(o0.x, 0.f); o0.y = fmaxf(o0.y, 0.f); o0.z = fmaxf(o0.z, 0.f); o0.w = fmaxf(o0.w, 0.f);
            o1.x = fmaxf(o1.x, 0.f); o1.y = fmaxf(o1.y, 0.f); o1.z = fmaxf(o1.z, 0.f); o1.w = fmaxf(o1.w, 0.f);
        }
        *(float4*)&C[(size_t)gm * N + gcol]     = o0;
        *(float4*)&C[(size_t)gm * N + gcol + 4] = o1;
    }
}

// ------------------------- flash attention: block = (qtile, h, b) -------------------------
__global__ void flash_attn_kernel(const float* __restrict__ qkv, float* __restrict__ out) {
    const int qt = blockIdx.x, h = blockIdx.y, b = blockIdx.z;
    const int t = threadIdx.x, w = t >> 5, lane = t & 31;

    __shared__ float Qs[64][33];
    __shared__ float Ks[64][33];
    __shared__ float Vs[64][33];

    const int q0 = qt * 64;
    const size_t basebq = (size_t)b * CQ;

    for (int i = t; i < 64 * 32; i += 256) {
        int r = i >> 5, c = i & 31;
        int gq = q0 + r;
        Qs[r][c] = (gq < CQ) ? qkv[(basebq + gq) * 768 + h * CDH + c] * ATTN_SCALE : 0.f;
    }

    float acc[8], mr[8], lr[8];
    #pragma unroll
    for (int i = 0; i < 8; i++) { acc[i] = 0.f; mr[i] = -1e30f; lr[i] = 0.f; }

    for (int k0 = 0; k0 < CQ; k0 += 64) {
        __syncthreads();
        for (int i = t; i < 64 * 32; i += 256) {
            int r = i >> 5, c = i & 31;
            int gk = k0 + r;
            if (gk < CQ) {
                const float* p = qkv + (basebq + gk) * 768 + h * CDH + c;
                Ks[r][c] = p[CD];
                Vs[r][c] = p[2 * CD];
            } else { Ks[r][c] = 0.f; Vs[r][c] = 0.f; }
        }
        __syncthreads();

        float s0[8], s1[8];
        #pragma unroll
        for (int i = 0; i < 8; i++) { s0[i] = 0.f; s1[i] = 0.f; }
        #pragma unroll
        for (int c = 0; c < 32; c++) {
            float k0v = Ks[lane][c];
            float k1v = Ks[32 + lane][c];
            #pragma unroll
            for (int i = 0; i < 8; i++) {
                float qv = Qs[w * 8 + i][c];
                s0[i] = fmaf(qv, k0v, s0[i]);
                s1[i] = fmaf(qv, k1v, s1[i]);
            }
        }

        #pragma unroll
        for (int u = 0; u < 2; u++) {
            const int kb = k0 + u * 32;
            const bool valid = (kb + lane) < CQ;
            float p[8];
            #pragma unroll
            for (int i = 0; i < 8; i++) {
                float sv = valid ? (u == 0 ? s0[i] : s1[i]) : -1e30f;
                float cm = sv;
                #pragma unroll
                for (int o = 16; o > 0; o >>= 1)
                    cm = fmaxf(cm, __shfl_xor_sync(0xffffffffu, cm, o));
                float nm = fmaxf(mr[i], cm);
                float f  = __expf(mr[i] - nm);
                float pv = __expf(sv - nm);
                float ps = pv;
                #pragma unroll
                for (int o = 16; o > 0; o >>= 1)
                    ps += __shfl_xor_sync(0xffffffffu, ps, o);
                lr[i] = lr[i] * f + ps;
                acc[i] *= f;
                mr[i] = nm;
                p[i] = pv;
            }
            #pragma unroll
            for (int k = 0; k < 32; k++) {
                float vv = Vs[u * 32 + k][lane];
                #pragma unroll
                for (int i = 0; i < 8; i++)
                    acc[i] = fmaf(__shfl_sync(0xffffffffu, p[i], k), vv, acc[i]);
            }
        }
    }

    #pragma unroll
    for (int i = 0; i < 8; i++) {
        int gq = q0 + w * 8 + i;
        if (gq < CQ)
            out[(basebq + gq) * CD + h * CDH + lane] = acc[i] / lr[i];
    }
}

// ------------------------- fused residual-add + LayerNorm -------------------------
__global__ void add_ln_kernel(const float* __restrict__ a, const float* __restrict__ r,
                              const float* __restrict__ g, const float* __restrict__ be,
                              float* __restrict__ out, float* __restrict__ out2) {
    int row = blockIdx.x, t = threadIdx.x;   // 256 threads, D=256
    size_t idx = (size_t)row * CD + t;
    float v = a[idx] + r[idx];

    __shared__ float red[8];
    __shared__ float stat[2];

    float s = v;
    #pragma unroll
    for (int o = 16; o > 0; o >>= 1) s += __shfl_xor_sync(0xffffffffu, s, o);
    if ((t & 31) == 0) red[t >> 5] = s;
    __syncthreads();
    if (t == 0) {
        float tot = 0.f;
        #pragma unroll
        for (int i = 0; i < 8; i++) tot += red[i];
        stat[0] = tot * (1.f / CD);
    }
    __syncthreads();
    float mu = stat[0];
    float d = v - mu;
    float s2 = d * d;
    #pragma unroll
    for (int o = 16; o > 0; o >>= 1) s2 += __shfl_xor_sync(0xffffffffu, s2, o);
    if ((t & 31) == 0) red[t >> 5] = s2;
    __syncthreads();
    if (t == 0) {
        float tot = 0.f;
        #pragma unroll
        for (int i = 0; i < 8; i++) tot += red[i];
        stat[1] = tot * (1.f / CD);
    }
    __syncthreads();
    float o = d * rsqrtf(stat[1] + 1e-5f) * g[t] + be[t];
    out[idx] = o;
    if (out2) out2[idx] = o;
}

// ------------------------- MSDA gather: one block per (b,q), warp = head -------------------------
__global__ void msda_kernel(const float* __restrict__ value, const float* __restrict__ off,
                            const float* __restrict__ awl, const float* __restrict__ refp,
                            const float* __restrict__ vr, float* __restrict__ out) {
    int bq = blockIdx.x;
    int b = bq / CQ;
    int t = threadIdx.x;          // 256 threads = 8 warps
    int h = t >> 5, lane = t & 31;

    float logit = (lane < 16) ? awl[(size_t)bq * 128 + h * 16 + lane] : -1e30f;
    float m = logit;
    #pragma unroll
    for (int o = 8; o > 0; o >>= 1) m = fmaxf(m, __shfl_xor_sync(0xffffffffu, m, o, 16));
    float e = (lane < 16) ? __expf(logit - m) : 0.f;
    float es = e;
    #pragma unroll
    for (int o = 8; o > 0; o >>= 1) es += __shfl_xor_sync(0xffffffffu, es, o, 16);
    float p = e / es;

    float rx = refp[(size_t)bq * 2 + 0];
    float ry = refp[(size_t)bq * 2 + 1];

    const int   Ws[4] = {100, 50, 25, 13};
    const int   Hs[4] = {100, 50, 25, 13};
    const int   ST[4] = {0, 10000, 12500, 13125};

    const float* voff = value + (size_t)b * CS * CD + h * CDH + lane;
    float acc = 0.f;

    #pragma unroll
    for (int l = 0; l < 4; l++) {
        int W_ = Ws[l], H_ = Hs[l], st = ST[l];
        float vrx = vr[b * 8 + l * 2 + 0];
        float vry = vr[b * 8 + l * 2 + 1];
        float bx = rx * vrx * (float)W_ - 0.5f;
        float by = ry * vry * (float)H_ - 0.5f;
        #pragma unroll
        for (int pp = 0; pp < 4; pp++) {
            size_t oidx = (size_t)bq * 256 + (size_t)(((h * 4 + l) * 4 + pp) * 2);
            float x = bx + off[oidx + 0];
            float y = by + off[oidx + 1];
            float w = __shfl_sync(0xffffffffu, p, l * 4 + pp, 32);
            float x0f = floorf(x), y0f = floorf(y);
            float wx = x - x0f, wy = y - y0f;
            int x0 = (int)x0f, y0 = (int)y0f;

            float gsum = 0.f;
            {
                int xi = x0, yi = y0;
                if (xi >= 0 && xi < W_ && yi >= 0 && yi < H_)
                    gsum = fmaf(voff[(size_t)(st + yi * W_ + xi) * CD], (1.f - wx) * (1.f - wy), gsum);
            }
            {
                int xi = x0 + 1, yi = y0;
                if (xi >= 0 && xi < W_ && yi >= 0 && yi < H_)
                    gsum = fmaf(voff[(size_t)(st + yi * W_ + xi) * CD], wx * (1.f - wy), gsum);
            }
            {
                int xi = x0, yi = y0 + 1;
                if (xi >= 0 && xi < W_ && yi >= 0 && yi < H_)
                    gsum = fmaf(voff[(size_t)(st + yi * W_ + xi) * CD], (1.f - wx) * wy, gsum);
            }
            {
                int xi = x0 + 1, yi = y0 + 1;
                if (xi >= 0 && xi < W_ && yi >= 0 && yi < H_)
                    gsum = fmaf(voff[(size_t)(st + yi * W_ + xi) * CD], wx * wy, gsum);
            }
            acc = fmaf(w, gsum, acc);
        }
    }
    out[(size_t)bq * CD + h * CDH + lane] = acc;
}

// ------------------------- inter_refs: reference_points repeated 6x -------------------------
__global__ void write_refs_kernel(const float* __restrict__ refp, float* __restrict__ out) {
    int i = blockIdx.x * blockDim.x + threadIdx.x;
    const int n = CB * CQ * 2;
    if (i < n) {
        float v = refp[i];
        #pragma unroll
        for (int L = 0; L < CNLAYERS; L++) out[(size_t)L * n + i] = v;
    }
}

// ------------------------- driver -------------------------
extern "C" void kernel_launch(void* const* d_in, const int* in_sizes, int n_in,
                              void* d_out, int out_size) {
    const float* tgt      = (const float*)d_in[0];
    const float* refp     = (const float*)d_in[1];
    const float* memory   = (const float*)d_in[2];
    const float* vratios  = (const float*)d_in[5];
    const float* qpos     = (const float*)d_in[6];
    const float* sa_in_w  = (const float*)d_in[7];
    const float* sa_in_b  = (const float*)d_in[8];
    const float* sa_out_w = (const float*)d_in[9];
    const float* sa_out_b = (const float*)d_in[10];
    const float* n1_g     = (const float*)d_in[11];
    const float* n1_b     = (const float*)d_in[12];
    const float* n2_g     = (const float*)d_in[13];
    const float* n2_b     = (const float*)d_in[14];
    const float* n3_g     = (const float*)d_in[15];
    const float* n3_b     = (const float*)d_in[16];
    const float* vp_w     = (const float*)d_in[17];
    const float* vp_b     = (const float*)d_in[18];
    const float* so_w     = (const float*)d_in[19];
    const float* so_b     = (const float*)d_in[20];
    const float* aw_w     = (const float*)d_in[21];
    const float* aw_b     = (const float*)d_in[22];
    const float* op_w     = (const float*)d_in[23];
    const float* op_b     = (const float*)d_in[24];
    const float* ff1_w    = (const float*)d_in[25];
    const float* ff1_b    = (const float*)d_in[26];
    const float* ff2_w    = (const float*)d_in[27];
    const float* ff2_b    = (const float*)d_in[28];

    float *value, *x, *xpq, *qkv, *attn, *t2, *off, *awl, *ms, *ffh;
    cudaGetSymbolAddress((void**)&value, g_value);
    cudaGetSymbolAddress((void**)&x,     g_x);
    cudaGetSymbolAddress((void**)&xpq,   g_xpq);
    cudaGetSymbolAddress((void**)&qkv,   g_qkv);
    cudaGetSymbolAddress((void**)&attn,  g_attn);
    cudaGetSymbolAddress((void**)&t2,    g_t2);
    cudaGetSymbolAddress((void**)&off,   g_off);
    cudaGetSymbolAddress((void**)&awl,   g_awl);
    cudaGetSymbolAddress((void**)&ms,    g_ms);
    cudaGetSymbolAddress((void**)&ffh,   g_ffh);

    float* out = (float*)d_out;

    cudaMemcpyAsync(x, tgt, sizeof(float) * CBQ * CD, cudaMemcpyDeviceToDevice, 0);

    // layer-invariant value projection (computed ONCE)
    gemm128<false><<<dim3(CD/128, (CBS + 127)/128), 256>>>(memory, vp_w, vp_b, value, CBS, CD, CD);

    write_refs_kernel<<<(CB*CQ*2 + 255)/256, 256>>>(refp, out + (size_t)CNLAYERS * CBQ * CD);

    const int MB = (CBQ + 127) / 128;   // 57 row-blocks

    for (int L = 0; L < CNLAYERS; L++) {
        add_kernel<<<(CBQ*CD + 255)/256, 256>>>(x, qpos, xpq, CBQ*CD);

        // ---- MHA ----
        gemm128<false><<<dim3(768/128, MB), 256>>>(xpq, sa_in_w, sa_in_b, qkv, CBQ, 3*CD, CD);
        flash_attn_kernel<<<dim3(15, CNH, CB), 256>>>(qkv, attn);
        gemm128<false><<<dim3(CD/128, MB), 256>>>(attn, sa_out_w, sa_out_b, t2, CBQ, CD, CD);
        add_ln_kernel<<<CBQ, CD>>>(xpq, t2, n1_g, n1_b, x, nullptr);

        // ---- MSDA ----
        gemm128<false><<<dim3(256/128, MB), 256>>>(x, so_w, so_b, off, CBQ, 256, CD);
        gemm128<false><<<dim3(128/128, MB), 256>>>(x, aw_w, aw_b, awl, CBQ, 128, CD);
        msda_kernel<<<CBQ, 256>>>(value, off, awl, refp, vratios, ms);
        gemm128<false><<<dim3(CD/128, MB), 256>>>(ms, op_w, op_b, t2, CBQ, CD, CD);
        add_ln_kernel<<<CBQ, CD>>>(x, t2, n2_g, n2_b, x, nullptr);

        // ---- FFN ----
        gemm128<true ><<<dim3(CFF/128, MB), 256>>>(x, ff1_w, ff1_b, ffh, CBQ, CFF, CD);
        gemm128<false><<<dim3(CD/128, MB), 256>>>(ffh, ff2_w, ff2_b, t2, CBQ, CD, CFF);
        add_ln_kernel<<<CBQ, CD>>>(x, t2, n3_g, n3_b, x, out + (size_t)L * CBQ * CD);
    }
}

// round 5
// speedup vs baseline: 8.0466x; 1.2723x over previous
#include <cuda_runtime.h>
#include <cuda_bf16.h>

// Problem constants
#define CB 8
#define CQ 900
#define CD 256
#define CNH 8
#define CDH 32
#define CFF 1024
#define CS 13294          // 100*100 + 50*50 + 25*25 + 13*13
#define CBQ (CB*CQ)       // 7200
#define CBS (CB*CS)       // 106352
#define CNLAYERS 6
#define ATTN_SCALE 0.17677669529663687f   // 1/sqrt(32)

// ------------------------- scratch (device globals) -------------------------
__device__ float g_value[CBS*CD];     // projected value, layer-invariant
__device__ float g_x   [CBQ*CD];      // decoder state
__device__ float g_xpq [CBQ*CD];      // x + query_pos
__device__ float g_qkv [CBQ*3*CD];
__device__ float g_attn[CBQ*CD];
__device__ float g_t2  [CBQ*CD];
__device__ float g_off [CBQ*256];     // sampling offsets
__device__ float g_awl [CBQ*128];     // attention-weight logits
__device__ float g_ms  [CBQ*CD];      // msda gather output
__device__ float g_ffh [CBQ*CFF];     // ffn hidden

// split-weight planes (packed bf16 pairs along K). offsets in uint32 pairs.
#define OFF_VP   0
#define OFF_SAIN (OFF_VP   + 32768)    // vp:   256*256/2
#define OFF_SAOU (OFF_SAIN + 98304)    // sain: 768*256/2
#define OFF_SO   (OFF_SAOU + 32768)
#define OFF_AW   (OFF_SO   + 32768)
#define OFF_OP   (OFF_AW   + 16384)
#define OFF_FF1  (OFF_OP   + 32768)
#define OFF_FF2  (OFF_FF1  + 131072)
#define WSPLIT_TOTAL (OFF_FF2 + 131072) // 507904
__device__ unsigned g_wh[WSPLIT_TOTAL];
__device__ unsigned g_wl[WSPLIT_TOTAL];

// ------------------------- bf16 split helpers -------------------------
__device__ __forceinline__ void split2(float x, float y, unsigned& hi, unsigned& lo) {
    __nv_bfloat162 h = __floats2bfloat162_rn(x, y);
    hi = *reinterpret_cast<unsigned*>(&h);
    float rx = x - __bfloat162float(h.x);
    float ry = y - __bfloat162float(h.y);
    __nv_bfloat162 l = __floats2bfloat162_rn(rx, ry);
    lo = *reinterpret_cast<unsigned*>(&l);
}

__device__ __forceinline__ void mma_bf16(float* d, const unsigned* a, unsigned b0, unsigned b1) {
    asm volatile(
        "mma.sync.aligned.m16n8k16.row.col.f32.bf16.bf16.f32 "
        "{%0,%1,%2,%3}, {%4,%5,%6,%7}, {%8,%9}, {%0,%1,%2,%3};"
        : "+f"(d[0]), "+f"(d[1]), "+f"(d[2]), "+f"(d[3])
        : "r"(a[0]), "r"(a[1]), "r"(a[2]), "r"(a[3]), "r"(b0), "r"(b1));
}

// ------------------------- weight split prep -------------------------
__global__ void split_w_kernel(const float* __restrict__ w, unsigned* __restrict__ oh,
                               unsigned* __restrict__ ol, int npairs) {
    int i = blockIdx.x * blockDim.x + threadIdx.x;
    if (i < npairs) {
        unsigned h, l;
        split2(w[2*i], w[2*i+1], h, l);
        oh[i] = h; ol[i] = l;
    }
}

// ------------------------- elementwise add -------------------------
__global__ void add_kernel(const float* __restrict__ a, const float* __restrict__ b,
                           float* __restrict__ o, int n) {
    int i = blockIdx.x * blockDim.x + threadIdx.x;
    if (i < n) o[i] = a[i] + b[i];
}

// ------------------------- bf16x3 tensor-core GEMM -------------------------
// C[M,N] = A[M,K] @ W[N,K]^T + bias ; W pre-split into packed bf16 hi/lo planes.
// N multiple of 128, K multiple of 32.
template<bool RELU>
__global__ __launch_bounds__(256)
void gemm_bf3(const float* __restrict__ A, const unsigned* __restrict__ Wh,
              const unsigned* __restrict__ Wl, const float* __restrict__ bias,
              float* __restrict__ C, int M, int N, int K) {
    __shared__ unsigned Ah[128][20];
    __shared__ unsigned Al[128][20];
    __shared__ unsigned Bh[128][20];
    __shared__ unsigned Bl[128][20];

    const int tid  = threadIdx.x;
    const int lane = tid & 31, warp = tid >> 5;
    const int g = lane >> 2, tg = lane & 3;
    const int warpM = warp & 1, warpN = warp >> 1;   // 2 x 4 warps
    const int m0 = warpM * 64, n0 = warpN * 32;
    const int rowBase = blockIdx.y * 128, colBase = blockIdx.x * 128;
    const int Kp = K >> 1;

    // loader mapping: 2 threads per row, 16 floats (8 pairs) each
    const int lrow  = tid >> 1;
    const int lhalf = tid & 1;
    const int kpb   = lhalf * 8;
    const int arow  = rowBase + lrow;
    const bool av   = arow < M;
    const float*    ap  = A  + (size_t)arow * K + lhalf * 16;
    const unsigned* bhp = Wh + (size_t)(colBase + lrow) * Kp + kpb;
    const unsigned* blp = Wl + (size_t)(colBase + lrow) * Kp + kpb;

    float acc[4][4][4];
    #pragma unroll
    for (int i = 0; i < 4; i++)
        #pragma unroll
        for (int j = 0; j < 4; j++)
            #pragma unroll
            for (int r = 0; r < 4; r++) acc[i][j][r] = 0.f;

    const float4 fz = make_float4(0.f, 0.f, 0.f, 0.f);
    float4 ra[4]; uint4 rbh[2], rbl[2];
    #pragma unroll
    for (int j = 0; j < 4; j++) ra[j] = av ? *(const float4*)(ap + 4*j) : fz;
    rbh[0] = *(const uint4*)(bhp);     rbh[1] = *(const uint4*)(bhp + 4);
    rbl[0] = *(const uint4*)(blp);     rbl[1] = *(const uint4*)(blp + 4);

    const int ntiles = K >> 5;
    for (int kt = 0; kt < ntiles; kt++) {
        // stage A (split to bf16 hi/lo) and B (already split) into smem
        #pragma unroll
        for (int j = 0; j < 4; j++) {
            unsigned h0, l0, h1, l1;
            split2(ra[j].x, ra[j].y, h0, l0);
            split2(ra[j].z, ra[j].w, h1, l1);
            Ah[lrow][kpb + 2*j]     = h0;  Ah[lrow][kpb + 2*j + 1] = h1;
            Al[lrow][kpb + 2*j]     = l0;  Al[lrow][kpb + 2*j + 1] = l1;
        }
        Bh[lrow][kpb+0] = rbh[0].x; Bh[lrow][kpb+1] = rbh[0].y;
        Bh[lrow][kpb+2] = rbh[0].z; Bh[lrow][kpb+3] = rbh[0].w;
        Bh[lrow][kpb+4] = rbh[1].x; Bh[lrow][kpb+5] = rbh[1].y;
        Bh[lrow][kpb+6] = rbh[1].z; Bh[lrow][kpb+7] = rbh[1].w;
        Bl[lrow][kpb+0] = rbl[0].x; Bl[lrow][kpb+1] = rbl[0].y;
        Bl[lrow][kpb+2] = rbl[0].z; Bl[lrow][kpb+3] = rbl[0].w;
        Bl[lrow][kpb+4] = rbl[1].x; Bl[lrow][kpb+5] = rbl[1].y;
        Bl[lrow][kpb+6] = rbl[1].z; Bl[lrow][kpb+7] = rbl[1].w;
        __syncthreads();

        // prefetch next tile
        if (kt + 1 < ntiles) {
            const int fo = (kt + 1) * 32;
            const int po = (kt + 1) * 16;
            #pragma unroll
            for (int j = 0; j < 4; j++) ra[j] = av ? *(const float4*)(ap + fo + 4*j) : fz;
            rbh[0] = *(const uint4*)(bhp + po); rbh[1] = *(const uint4*)(bhp + po + 4);
            rbl[0] = *(const uint4*)(blp + po); rbl[1] = *(const uint4*)(blp + po + 4);
        }

        #pragma unroll
        for (int ks = 0; ks < 2; ks++) {
            const int kq = ks * 8 + tg;
            unsigned af[4][4], alf[4][4];
            #pragma unroll
            for (int mt = 0; mt < 4; mt++) {
                const int mm = m0 + mt * 16 + g;
                af[mt][0]  = Ah[mm][kq];   af[mt][1]  = Ah[mm+8][kq];
                af[mt][2]  = Ah[mm][kq+4]; af[mt][3]  = Ah[mm+8][kq+4];
                alf[mt][0] = Al[mm][kq];   alf[mt][1] = Al[mm+8][kq];
                alf[mt][2] = Al[mm][kq+4]; alf[mt][3] = Al[mm+8][kq+4];
            }
            #pragma unroll
            for (int nt = 0; nt < 4; nt++) {
                const int nn = n0 + nt * 8 + g;
                const unsigned bh0 = Bh[nn][kq], bh1 = Bh[nn][kq+4];
                const unsigned bl0 = Bl[nn][kq], bl1 = Bl[nn][kq+4];
                #pragma unroll
                for (int mt = 0; mt < 4; mt++) mma_bf16(acc[mt][nt], alf[mt], bh0, bh1);
                #pragma unroll
                for (int mt = 0; mt < 4; mt++) mma_bf16(acc[mt][nt], af[mt],  bl0, bl1);
                #pragma unroll
                for (int mt = 0; mt < 4; mt++) mma_bf16(acc[mt][nt], af[mt],  bh0, bh1);
            }
        }
        __syncthreads();
    }

    // epilogue
    #pragma unroll
    for (int mt = 0; mt < 4; mt++) {
        const int m  = rowBase + m0 + mt * 16 + g;
        #pragma unroll
        for (int nt = 0; nt < 4; nt++) {
            const int n = colBase + n0 + nt * 8 + 2 * tg;
            const float2 bv = *(const float2*)&bias[n];
            float* c = acc[mt][nt];
            if (m < M) {
                float2 o0 = make_float2(c[0] + bv.x, c[1] + bv.y);
                if (RELU) { o0.x = fmaxf(o0.x, 0.f); o0.y = fmaxf(o0.y, 0.f); }
                *(float2*)&C[(size_t)m * N + n] = o0;
            }
            if (m + 8 < M) {
                float2 o1 = make_float2(c[2] + bv.x, c[3] + bv.y);
                if (RELU) { o1.x = fmaxf(o1.x, 0.f); o1.y = fmaxf(o1.y, 0.f); }
                *(float2*)&C[(size_t)(m + 8) * N + n] = o1;
            }
        }
    }
}

// ------------------------- flash attention: block = (qtile, h, b) -------------------------
__global__ void flash_attn_kernel(const float* __restrict__ qkv, float* __restrict__ out) {
    const int qt = blockIdx.x, h = blockIdx.y, b = blockIdx.z;
    const int t = threadIdx.x, w = t >> 5, lane = t & 31;

    __shared__ float Qs[64][33];
    __shared__ float Ks[64][33];
    __shared__ float Vs[64][33];

    const int q0 = qt * 64;
    const size_t basebq = (size_t)b * CQ;

    for (int i = t; i < 64 * 32; i += 256) {
        int r = i >> 5, c = i & 31;
        int gq = q0 + r;
        Qs[r][c] = (gq < CQ) ? qkv[(basebq + gq) * 768 + h * CDH + c] * ATTN_SCALE : 0.f;
    }

    float acc[8], mr[8], lr[8];
    #pragma unroll
    for (int i = 0; i < 8; i++) { acc[i] = 0.f; mr[i] = -1e30f; lr[i] = 0.f; }

    for (int k0 = 0; k0 < CQ; k0 += 64) {
        __syncthreads();
        for (int i = t; i < 64 * 32; i += 256) {
            int r = i >> 5, c = i & 31;
            int gk = k0 + r;
            if (gk < CQ) {
                const float* p = qkv + (basebq + gk) * 768 + h * CDH + c;
                Ks[r][c] = p[CD];
                Vs[r][c] = p[2 * CD];
            } else { Ks[r][c] = 0.f; Vs[r][c] = 0.f; }
        }
        __syncthreads();

        float s0[8], s1[8];
        #pragma unroll
        for (int i = 0; i < 8; i++) { s0[i] = 0.f; s1[i] = 0.f; }
        #pragma unroll
        for (int c = 0; c < 32; c++) {
            float k0v = Ks[lane][c];
            float k1v = Ks[32 + lane][c];
            #pragma unroll
            for (int i = 0; i < 8; i++) {
                float qv = Qs[w * 8 + i][c];
                s0[i] = fmaf(qv, k0v, s0[i]);
                s1[i] = fmaf(qv, k1v, s1[i]);
            }
        }

        #pragma unroll
        for (int u = 0; u < 2; u++) {
            const int kb = k0 + u * 32;
            const bool valid = (kb + lane) < CQ;
            float p[8];
            #pragma unroll
            for (int i = 0; i < 8; i++) {
                float sv = valid ? (u == 0 ? s0[i] : s1[i]) : -1e30f;
                float cm = sv;
                #pragma unroll
                for (int o = 16; o > 0; o >>= 1)
                    cm = fmaxf(cm, __shfl_xor_sync(0xffffffffu, cm, o));
                float nm = fmaxf(mr[i], cm);
                float f  = __expf(mr[i] - nm);
                float pv = __expf(sv - nm);
                float ps = pv;
                #pragma unroll
                for (int o = 16; o > 0; o >>= 1)
                    ps += __shfl_xor_sync(0xffffffffu, ps, o);
                lr[i] = lr[i] * f + ps;
                acc[i] *= f;
                mr[i] = nm;
                p[i] = pv;
            }
            #pragma unroll
            for (int k = 0; k < 32; k++) {
                float vv = Vs[u * 32 + k][lane];
                #pragma unroll
                for (int i = 0; i < 8; i++)
                    acc[i] = fmaf(__shfl_sync(0xffffffffu, p[i], k), vv, acc[i]);
            }
        }
    }

    #pragma unroll
    for (int i = 0; i < 8; i++) {
        int gq = q0 + w * 8 + i;
        if (gq < CQ)
            out[(basebq + gq) * CD + h * CDH + lane] = acc[i] / lr[i];
    }
}

// ------------------------- fused residual-add + LayerNorm -------------------------
__global__ void add_ln_kernel(const float* __restrict__ a, const float* __restrict__ r,
                              const float* __restrict__ g, const float* __restrict__ be,
                              float* __restrict__ out, float* __restrict__ out2) {
    int row = blockIdx.x, t = threadIdx.x;   // 256 threads, D=256
    size_t idx = (size_t)row * CD + t;
    float v = a[idx] + r[idx];

    __shared__ float red[8];
    __shared__ float stat[2];

    float s = v;
    #pragma unroll
    for (int o = 16; o > 0; o >>= 1) s += __shfl_xor_sync(0xffffffffu, s, o);
    if ((t & 31) == 0) red[t >> 5] = s;
    __syncthreads();
    if (t == 0) {
        float tot = 0.f;
        #pragma unroll
        for (int i = 0; i < 8; i++) tot += red[i];
        stat[0] = tot * (1.f / CD);
    }
    __syncthreads();
    float mu = stat[0];
    float d = v - mu;
    float s2 = d * d;
    #pragma unroll
    for (int o = 16; o > 0; o >>= 1) s2 += __shfl_xor_sync(0xffffffffu, s2, o);
    if ((t & 31) == 0) red[t >> 5] = s2;
    __syncthreads();
    if (t == 0) {
        float tot = 0.f;
        #pragma unroll
        for (int i = 0; i < 8; i++) tot += red[i];
        stat[1] = tot * (1.f / CD);
    }
    __syncthreads();
    float o = d * rsqrtf(stat[1] + 1e-5f) * g[t] + be[t];
    out[idx] = o;
    if (out2) out2[idx] = o;
}

// ------------------------- MSDA gather: one block per (b,q), warp = head -------------------------
__global__ void msda_kernel(const float* __restrict__ value, const float* __restrict__ off,
                            const float* __restrict__ awl, const float* __restrict__ refp,
                            const float* __restrict__ vr, float* __restrict__ out) {
    int bq = blockIdx.x;
    int b = bq / CQ;
    int t = threadIdx.x;          // 256 threads = 8 warps
    int h = t >> 5, lane = t & 31;

    float logit = (lane < 16) ? awl[(size_t)bq * 128 + h * 16 + lane] : -1e30f;
    float m = logit;
    #pragma unroll
    for (int o = 8; o > 0; o >>= 1) m = fmaxf(m, __shfl_xor_sync(0xffffffffu, m, o, 16));
    float e = (lane < 16) ? __expf(logit - m) : 0.f;
    float es = e;
    #pragma unroll
    for (int o = 8; o > 0; o >>= 1) es += __shfl_xor_sync(0xffffffffu, es, o, 16);
    float p = e / es;

    float rx = refp[(size_t)bq * 2 + 0];
    float ry = refp[(size_t)bq * 2 + 1];

    const int   Ws[4] = {100, 50, 25, 13};
    const int   Hs[4] = {100, 50, 25, 13};
    const int   ST[4] = {0, 10000, 12500, 13125};

    const float* voff = value + (size_t)b * CS * CD + h * CDH + lane;
    float acc = 0.f;

    #pragma unroll
    for (int l = 0; l < 4; l++) {
        int W_ = Ws[l], H_ = Hs[l], st = ST[l];
        float vrx = vr[b * 8 + l * 2 + 0];
        float vry = vr[b * 8 + l * 2 + 1];
        float bx = rx * vrx * (float)W_ - 0.5f;
        float by = ry * vry * (float)H_ - 0.5f;
        #pragma unroll
        for (int pp = 0; pp < 4; pp++) {
            size_t oidx = (size_t)bq * 256 + (size_t)(((h * 4 + l) * 4 + pp) * 2);
            float x = bx + off[oidx + 0];
            float y = by + off[oidx + 1];
            float w = __shfl_sync(0xffffffffu, p, l * 4 + pp, 32);
            float x0f = floorf(x), y0f = floorf(y);
            float wx = x - x0f, wy = y - y0f;
            int x0 = (int)x0f, y0 = (int)y0f;

            float gsum = 0.f;
            {
                int xi = x0, yi = y0;
                if (xi >= 0 && xi < W_ && yi >= 0 && yi < H_)
                    gsum = fmaf(voff[(size_t)(st + yi * W_ + xi) * CD], (1.f - wx) * (1.f - wy), gsum);
            }
            {
                int xi = x0 + 1, yi = y0;
                if (xi >= 0 && xi < W_ && yi >= 0 && yi < H_)
                    gsum = fmaf(voff[(size_t)(st + yi * W_ + xi) * CD], wx * (1.f - wy), gsum);
            }
            {
                int xi = x0, yi = y0 + 1;
                if (xi >= 0 && xi < W_ && yi >= 0 && yi < H_)
                    gsum = fmaf(voff[(size_t)(st + yi * W_ + xi) * CD], (1.f - wx) * wy, gsum);
            }
            {
                int xi = x0 + 1, yi = y0 + 1;
                if (xi >= 0 && xi < W_ && yi >= 0 && yi < H_)
                    gsum = fmaf(voff[(size_t)(st + yi * W_ + xi) * CD], wx * wy, gsum);
            }
            acc = fmaf(w, gsum, acc);
        }
    }
    out[(size_t)bq * CD + h * CDH + lane] = acc;
}

// ------------------------- inter_refs: reference_points repeated 6x -------------------------
__global__ void write_refs_kernel(const float* __restrict__ refp, float* __restrict__ out) {
    int i = blockIdx.x * blockDim.x + threadIdx.x;
    const int n = CB * CQ * 2;
    if (i < n) {
        float v = refp[i];
        #pragma unroll
        for (int L = 0; L < CNLAYERS; L++) out[(size_t)L * n + i] = v;
    }
}

// ------------------------- driver -------------------------
extern "C" void kernel_launch(void* const* d_in, const int* in_sizes, int n_in,
                              void* d_out, int out_size) {
    const float* tgt      = (const float*)d_in[0];
    const float* refp     = (const float*)d_in[1];
    const float* memory   = (const float*)d_in[2];
    const float* vratios  = (const float*)d_in[5];
    const float* qpos     = (const float*)d_in[6];
    const float* sa_in_w  = (const float*)d_in[7];
    const float* sa_in_b  = (const float*)d_in[8];
    const float* sa_out_w = (const float*)d_in[9];
    const float* sa_out_b = (const float*)d_in[10];
    const float* n1_g     = (const float*)d_in[11];
    const float* n1_b     = (const float*)d_in[12];
    const float* n2_g     = (const float*)d_in[13];
    const float* n2_b     = (const float*)d_in[14];
    const float* n3_g     = (const float*)d_in[15];
    const float* n3_b     = (const float*)d_in[16];
    const float* vp_w     = (const float*)d_in[17];
    const float* vp_b     = (const float*)d_in[18];
    const float* so_w     = (const float*)d_in[19];
    const float* so_b     = (const float*)d_in[20];
    const float* aw_w     = (const float*)d_in[21];
    const float* aw_b     = (const float*)d_in[22];
    const float* op_w     = (const float*)d_in[23];
    const float* op_b     = (const float*)d_in[24];
    const float* ff1_w    = (const float*)d_in[25];
    const float* ff1_b    = (const float*)d_in[26];
    const float* ff2_w    = (const float*)d_in[27];
    const float* ff2_b    = (const float*)d_in[28];

    float *value, *x, *xpq, *qkv, *attn, *t2, *off, *awl, *ms, *ffh;
    unsigned *wh, *wl;
    cudaGetSymbolAddress((void**)&value, g_value);
    cudaGetSymbolAddress((void**)&x,     g_x);
    cudaGetSymbolAddress((void**)&xpq,   g_xpq);
    cudaGetSymbolAddress((void**)&qkv,   g_qkv);
    cudaGetSymbolAddress((void**)&attn,  g_attn);
    cudaGetSymbolAddress((void**)&t2,    g_t2);
    cudaGetSymbolAddress((void**)&off,   g_off);
    cudaGetSymbolAddress((void**)&awl,   g_awl);
    cudaGetSymbolAddress((void**)&ms,    g_ms);
    cudaGetSymbolAddress((void**)&ffh,   g_ffh);
    cudaGetSymbolAddress((void**)&wh,    g_wh);
    cudaGetSymbolAddress((void**)&wl,    g_wl);

    float* out = (float*)d_out;

    cudaMemcpyAsync(x, tgt, sizeof(float) * CBQ * CD, cudaMemcpyDeviceToDevice, 0);

    // split all weights into bf16 hi/lo planes (weights shared across layers)
    #define SPLITW(ptr, offp, npairs) \
        split_w_kernel<<<((npairs) + 255)/256, 256>>>(ptr, wh + (offp), wl + (offp), npairs)
    SPLITW(vp_w,     OFF_VP,   32768);
    SPLITW(sa_in_w,  OFF_SAIN, 98304);
    SPLITW(sa_out_w, OFF_SAOU, 32768);
    SPLITW(so_w,     OFF_SO,   32768);
    SPLITW(aw_w,     OFF_AW,   16384);
    SPLITW(op_w,     OFF_OP,   32768);
    SPLITW(ff1_w,    OFF_FF1,  131072);
    SPLITW(ff2_w,    OFF_FF2,  131072);

    // layer-invariant value projection (computed ONCE)
    gemm_bf3<false><<<dim3(CD/128, (CBS + 127)/128), 256>>>(
        memory, wh + OFF_VP, wl + OFF_VP, vp_b, value, CBS, CD, CD);

    write_refs_kernel<<<(CB*CQ*2 + 255)/256, 256>>>(refp, out + (size_t)CNLAYERS * CBQ * CD);

    const int MB = (CBQ + 127) / 128;   // 57 row-blocks

    for (int L = 0; L < CNLAYERS; L++) {
        add_kernel<<<(CBQ*CD + 255)/256, 256>>>(x, qpos, xpq, CBQ*CD);

        // ---- MHA ----
        gemm_bf3<false><<<dim3(768/128, MB), 256>>>(
            xpq, wh + OFF_SAIN, wl + OFF_SAIN, sa_in_b, qkv, CBQ, 3*CD, CD);
        flash_attn_kernel<<<dim3(15, CNH, CB), 256>>>(qkv, attn);
        gemm_bf3<false><<<dim3(CD/128, MB), 256>>>(
            attn, wh + OFF_SAOU, wl + OFF_SAOU, sa_out_b, t2, CBQ, CD, CD);
        add_ln_kernel<<<CBQ, CD>>>(xpq, t2, n1_g, n1_b, x, nullptr);

        // ---- MSDA ----
        gemm_bf3<false><<<dim3(256/128, MB), 256>>>(
            x, wh + OFF_SO, wl + OFF_SO, so_b, off, CBQ, 256, CD);
        gemm_bf3<false><<<dim3(128/128, MB), 256>>>(
            x, wh + OFF_AW, wl + OFF_AW, aw_b, awl, CBQ, 128, CD);
        msda_kernel<<<CBQ, 256>>>(value, off, awl, refp, vratios, ms);
        gemm_bf3<false><<<dim3(CD/128, MB), 256>>>(
            ms, wh + OFF_OP, wl + OFF_OP, op_b, t2, CBQ, CD, CD);
        add_ln_kernel<<<CBQ, CD>>>(x, t2, n2_g, n2_b, x, nullptr);

        // ---- FFN ----
        gemm_bf3<true ><<<dim3(CFF/128, MB), 256>>>(
            x, wh + OFF_FF1, wl + OFF_FF1, ff1_b, ffh, CBQ, CFF, CD);
        gemm_bf3<false><<<dim3(CD/128, MB), 256>>>(
            ffh, wh + OFF_FF2, wl + OFF_FF2, ff2_b, t2, CBQ, CD, CFF);
        add_ln_kernel<<<CBQ, CD>>>(x, t2, n3_g, n3_b, x, out + (size_t)L * CBQ * CD);
    }
}

// round 7
// speedup vs baseline: 13.5261x; 1.6810x over previous
#include <cuda_runtime.h>
#include <cuda_bf16.h>

// Problem constants
#define CB 8
#define CQ 900
#define CD 256
#define CNH 8
#define CDH 32
#define CFF 1024
#define CS 13294          // 100*100 + 50*50 + 25*25 + 13*13
#define CBQ (CB*CQ)       // 7200
#define CBS (CB*CS)       // 106352
#define CNLAYERS 6
#define ATTN_SCALE 0.17677669529663687f   // 1/sqrt(32)

// ------------------------- scratch (device globals) -------------------------
__device__ float g_value[CBS*CD];     // projected value, layer-invariant
__device__ float g_x    [CBQ*CD];     // decoder state
__device__ float g_xpq  [CBQ*CD];     // x + query_pos
__device__ float g_qkv  [CBQ*3*CD];
__device__ float g_attn [CBQ*CD];
__device__ float g_t2   [CBQ*CD];
__device__ float g_offaw[CBQ*384];    // fused sampling offsets (256) + aw logits (128)
__device__ float g_ms   [CBQ*CD];     // msda gather output
__device__ float g_ffh  [CBQ*CFF];    // ffn hidden
__device__ float g_sob  [384];        // concatenated so_b | aw_b

// split-weight planes (packed bf16 pairs along K). offsets in uint32 pairs.
#define OFF_VP   0
#define OFF_SAIN (OFF_VP   + 32768)    // vp:   256*256/2
#define OFF_SAOU (OFF_SAIN + 98304)    // sain: 768*256/2
#define OFF_SO   (OFF_SAOU + 32768)    // so+aw combined: 384*256/2
#define OFF_AW   (OFF_SO   + 32768)    // aw block lives right after so block
#define OFF_OP   (OFF_AW   + 16384)
#define OFF_FF1  (OFF_OP   + 32768)
#define OFF_FF2  (OFF_FF1  + 131072)
#define WSPLIT_TOTAL (OFF_FF2 + 131072) // 507904
__device__ unsigned g_wh[WSPLIT_TOTAL];
__device__ unsigned g_wl[WSPLIT_TOTAL];

// ------------------------- bf16 split helpers -------------------------
__device__ __forceinline__ void split2(float x, float y, unsigned& hi, unsigned& lo) {
    __nv_bfloat162 h = __floats2bfloat162_rn(x, y);
    hi = *reinterpret_cast<unsigned*>(&h);
    float rx = x - __bfloat162float(h.x);
    float ry = y - __bfloat162float(h.y);
    __nv_bfloat162 l = __floats2bfloat162_rn(rx, ry);
    lo = *reinterpret_cast<unsigned*>(&l);
}

__device__ __forceinline__ void mma_bf16(float* d, const unsigned* a, unsigned b0, unsigned b1) {
    asm volatile(
        "mma.sync.aligned.m16n8k16.row.col.f32.bf16.bf16.f32 "
        "{%0,%1,%2,%3}, {%4,%5,%6,%7}, {%8,%9}, {%0,%1,%2,%3};"
        : "+f"(d[0]), "+f"(d[1]), "+f"(d[2]), "+f"(d[3])
        : "r"(a[0]), "r"(a[1]), "r"(a[2]), "r"(a[3]), "r"(b0), "r"(b1));
}

// ------------------------- weight split prep -------------------------
__global__ void split_w_kernel(const float* __restrict__ w, unsigned* __restrict__ oh,
                               unsigned* __restrict__ ol, int npairs) {
    int i = blockIdx.x * blockDim.x + threadIdx.x;
    if (i < npairs) {
        unsigned h, l;
        split2(w[2*i], w[2*i+1], h, l);
        oh[i] = h; ol[i] = l;
    }
}

__global__ void concat_bias_kernel(const float* __restrict__ a, const float* __restrict__ b,
                                   float* __restrict__ o) {
    int i = blockIdx.x * blockDim.x + threadIdx.x;
    if (i < 256) o[i] = a[i];
    else if (i < 384) o[i] = b[i - 256];
}

// ------------------------- elementwise add -------------------------
__global__ void add_kernel(const float* __restrict__ a, const float* __restrict__ b,
                           float* __restrict__ o, int n) {
    int i = blockIdx.x * blockDim.x + threadIdx.x;
    if (i < n) o[i] = a[i] + b[i];
}

// ------------------------- bf16x3 tensor-core GEMM -------------------------
// C[M,N] = A[M,K] @ W[N,K]^T + bias ; W pre-split into packed bf16 hi/lo planes.
// N multiple of 128, K multiple of 32.
template<bool RELU>
__global__ __launch_bounds__(256)
void gemm_bf3(const float* __restrict__ A, const unsigned* __restrict__ Wh,
              const unsigned* __restrict__ Wl, const float* __restrict__ bias,
              float* __restrict__ C, int M, int N, int K) {
    __shared__ unsigned Ah[128][20];
    __shared__ unsigned Al[128][20];
    __shared__ unsigned Bh[128][20];
    __shared__ unsigned Bl[128][20];

    const int tid  = threadIdx.x;
    const int lane = tid & 31, warp = tid >> 5;
    const int g = lane >> 2, tg = lane & 3;
    const int warpM = warp & 1, warpN = warp >> 1;   // 2 x 4 warps
    const int m0 = warpM * 64, n0 = warpN * 32;
    const int rowBase = blockIdx.y * 128, colBase = blockIdx.x * 128;
    const int Kp = K >> 1;

    const int lrow  = tid >> 1;
    const int lhalf = tid & 1;
    const int kpb   = lhalf * 8;
    const int arow  = rowBase + lrow;
    const bool av   = arow < M;
    const float*    ap  = A  + (size_t)arow * K + lhalf * 16;
    const unsigned* bhp = Wh + (size_t)(colBase + lrow) * Kp + kpb;
    const unsigned* blp = Wl + (size_t)(colBase + lrow) * Kp + kpb;

    float acc[4][4][4];
    #pragma unroll
    for (int i = 0; i < 4; i++)
        #pragma unroll
        for (int j = 0; j < 4; j++)
            #pragma unroll
            for (int r = 0; r < 4; r++) acc[i][j][r] = 0.f;

    const float4 fz = make_float4(0.f, 0.f, 0.f, 0.f);
    float4 ra[4]; uint4 rbh[2], rbl[2];
    #pragma unroll
    for (int j = 0; j < 4; j++) ra[j] = av ? *(const float4*)(ap + 4*j) : fz;
    rbh[0] = *(const uint4*)(bhp);     rbh[1] = *(const uint4*)(bhp + 4);
    rbl[0] = *(const uint4*)(blp);     rbl[1] = *(const uint4*)(blp + 4);

    const int ntiles = K >> 5;
    for (int kt = 0; kt < ntiles; kt++) {
        #pragma unroll
        for (int j = 0; j < 4; j++) {
            unsigned h0, l0, h1, l1;
            split2(ra[j].x, ra[j].y, h0, l0);
            split2(ra[j].z, ra[j].w, h1, l1);
            Ah[lrow][kpb + 2*j]     = h0;  Ah[lrow][kpb + 2*j + 1] = h1;
            Al[lrow][kpb + 2*j]     = l0;  Al[lrow][kpb + 2*j + 1] = l1;
        }
        Bh[lrow][kpb+0] = rbh[0].x; Bh[lrow][kpb+1] = rbh[0].y;
        Bh[lrow][kpb+2] = rbh[0].z; Bh[lrow][kpb+3] = rbh[0].w;
        Bh[lrow][kpb+4] = rbh[1].x; Bh[lrow][kpb+5] = rbh[1].y;
        Bh[lrow][kpb+6] = rbh[1].z; Bh[lrow][kpb+7] = rbh[1].w;
        Bl[lrow][kpb+0] = rbl[0].x; Bl[lrow][kpb+1] = rbl[0].y;
        Bl[lrow][kpb+2] = rbl[0].z; Bl[lrow][kpb+3] = rbl[0].w;
        Bl[lrow][kpb+4] = rbl[1].x; Bl[lrow][kpb+5] = rbl[1].y;
        Bl[lrow][kpb+6] = rbl[1].z; Bl[lrow][kpb+7] = rbl[1].w;
        __syncthreads();

        if (kt + 1 < ntiles) {
            const int fo = (kt + 1) * 32;
            const int po = (kt + 1) * 16;
            #pragma unroll
            for (int j = 0; j < 4; j++) ra[j] = av ? *(const float4*)(ap + fo + 4*j) : fz;
            rbh[0] = *(const uint4*)(bhp + po); rbh[1] = *(const uint4*)(bhp + po + 4);
            rbl[0] = *(const uint4*)(blp + po); rbl[1] = *(const uint4*)(blp + po + 4);
        }

        #pragma unroll
        for (int ks = 0; ks < 2; ks++) {
            const int kq = ks * 8 + tg;
            unsigned af[4][4], alf[4][4];
            #pragma unroll
            for (int mt = 0; mt < 4; mt++) {
                const int mm = m0 + mt * 16 + g;
                af[mt][0]  = Ah[mm][kq];   af[mt][1]  = Ah[mm+8][kq];
                af[mt][2]  = Ah[mm][kq+4]; af[mt][3]  = Ah[mm+8][kq+4];
                alf[mt][0] = Al[mm][kq];   alf[mt][1] = Al[mm+8][kq];
                alf[mt][2] = Al[mm][kq+4]; alf[mt][3] = Al[mm+8][kq+4];
            }
            #pragma unroll
            for (int nt = 0; nt < 4; nt++) {
                const int nn = n0 + nt * 8 + g;
                const unsigned bh0 = Bh[nn][kq], bh1 = Bh[nn][kq+4];
                const unsigned bl0 = Bl[nn][kq], bl1 = Bl[nn][kq+4];
                #pragma unroll
                for (int mt = 0; mt < 4; mt++) mma_bf16(acc[mt][nt], alf[mt], bh0, bh1);
                #pragma unroll
                for (int mt = 0; mt < 4; mt++) mma_bf16(acc[mt][nt], af[mt],  bl0, bl1);
                #pragma unroll
                for (int mt = 0; mt < 4; mt++) mma_bf16(acc[mt][nt], af[mt],  bh0, bh1);
            }
        }
        __syncthreads();
    }

    #pragma unroll
    for (int mt = 0; mt < 4; mt++) {
        const int m  = rowBase + m0 + mt * 16 + g;
        #pragma unroll
        for (int nt = 0; nt < 4; nt++) {
            const int n = colBase + n0 + nt * 8 + 2 * tg;
            const float2 bv = *(const float2*)&bias[n];
            float* c = acc[mt][nt];
            if (m < M) {
                float2 o0 = make_float2(c[0] + bv.x, c[1] + bv.y);
                if (RELU) { o0.x = fmaxf(o0.x, 0.f); o0.y = fmaxf(o0.y, 0.f); }
                *(float2*)&C[(size_t)m * N + n] = o0;
            }
            if (m + 8 < M) {
                float2 o1 = make_float2(c[2] + bv.x, c[3] + bv.y);
                if (RELU) { o1.x = fmaxf(o1.x, 0.f); o1.y = fmaxf(o1.y, 0.f); }
                *(float2*)&C[(size_t)(m + 8) * N + n] = o1;
            }
        }
    }
}

// ------------------------- tensor-core flash attention -------------------------
// Block = (qtile 64, h, b), 128 threads = 4 warps; warp owns 16 q rows.
// bf16x3 for QK^T and P.V (hi/lo split on Q, K, P, V) -> fp32-class accuracy.
__global__ __launch_bounds__(128)
void flash_attn_tc(const float* __restrict__ qkv, float* __restrict__ out) {
    const int qt = blockIdx.x, h = blockIdx.y, b = blockIdx.z;
    const int t = threadIdx.x, lane = t & 31, warp = t >> 5;
    const int g = lane >> 2, tg = lane & 3;

    __shared__ unsigned Qh[64][20], Ql[64][20];
    __shared__ unsigned Kh[64][20], Kl[64][20];
    __shared__ unsigned VTh[32][36], VTl[32][36];   // [dim][keypair 0..31], stride 36 conflict-free

    const int q0 = qt * 64;
    const size_t basebq = (size_t)b * CQ;
    const int r = t >> 1, half = t & 1;

    // ---- load Q tile (pre-scaled), split hi/lo ----
    {
        const int gq = q0 + r;
        float4 v[4];
        if (gq < CQ) {
            const float* p = qkv + (basebq + gq) * 768 + h * CDH + half * 16;
            #pragma unroll
            for (int j = 0; j < 4; j++) v[j] = *(const float4*)(p + 4*j);
        } else {
            #pragma unroll
            for (int j = 0; j < 4; j++) v[j] = make_float4(0.f,0.f,0.f,0.f);
        }
        #pragma unroll
        for (int j = 0; j < 4; j++) {
            unsigned h0, l0, h1, l1;
            split2(v[j].x * ATTN_SCALE, v[j].y * ATTN_SCALE, h0, l0);
            split2(v[j].z * ATTN_SCALE, v[j].w * ATTN_SCALE, h1, l1);
            Qh[r][half*8 + 2*j]     = h0;  Qh[r][half*8 + 2*j + 1] = h1;
            Ql[r][half*8 + 2*j]     = l0;  Ql[r][half*8 + 2*j + 1] = l1;
        }
    }
    __syncthreads();

    // Q fragments (persist across k-tiles)
    unsigned qh[2][4], ql[2][4];
    const int m0 = warp * 16;
    #pragma unroll
    for (int kc = 0; kc < 2; kc++) {
        const int kq = kc * 8 + tg;
        qh[kc][0] = Qh[m0+g][kq];   qh[kc][1] = Qh[m0+g+8][kq];
        qh[kc][2] = Qh[m0+g][kq+4]; qh[kc][3] = Qh[m0+g+8][kq+4];
        ql[kc][0] = Ql[m0+g][kq];   ql[kc][1] = Ql[m0+g+8][kq];
        ql[kc][2] = Ql[m0+g][kq+4]; ql[kc][3] = Ql[m0+g+8][kq+4];
    }

    float o[4][4];
    #pragma unroll
    for (int i = 0; i < 4; i++)
        #pragma unroll
        for (int j = 0; j < 4; j++) o[i][j] = 0.f;
    float m0r = -1e30f, m1r = -1e30f, l0r = 0.f, l1r = 0.f;

    for (int k0 = 0; k0 < CQ; k0 += 64) {
        __syncthreads();   // previous iteration's frag reads done

        // ---- load K tile, split hi/lo ----
        {
            const int gk = k0 + r;
            float4 v[4];
            if (gk < CQ) {
                const float* p = qkv + (basebq + gk) * 768 + CD + h * CDH + half * 16;
                #pragma unroll
                for (int j = 0; j < 4; j++) v[j] = *(const float4*)(p + 4*j);
            } else {
                #pragma unroll
                for (int j = 0; j < 4; j++) v[j] = make_float4(0.f,0.f,0.f,0.f);
            }
            #pragma unroll
            for (int j = 0; j < 4; j++) {
                unsigned h0, l0, h1, l1;
                split2(v[j].x, v[j].y, h0, l0);
                split2(v[j].z, v[j].w, h1, l1);
                Kh[r][half*8 + 2*j]     = h0;  Kh[r][half*8 + 2*j + 1] = h1;
                Kl[r][half*8 + 2*j]     = l0;  Kl[r][half*8 + 2*j + 1] = l1;
            }
        }

        // ---- load V tile, transpose to [dim][keypair] via shfl pairing ----
        {
            const int gk = k0 + r;
            float rv[16];
            if (gk < CQ) {
                const float* p = qkv + (basebq + gk) * 768 + 2*CD + h * CDH + half * 16;
                #pragma unroll
                for (int j = 0; j < 4; j++) {
                    float4 v = *(const float4*)(p + 4*j);
                    rv[4*j+0] = v.x; rv[4*j+1] = v.y; rv[4*j+2] = v.z; rv[4*j+3] = v.w;
                }
            } else {
                #pragma unroll
                for (int j = 0; j < 16; j++) rv[j] = 0.f;
            }
            const int kp = t >> 2;          // keypair this (even) thread writes (0..31)
            #pragma unroll
            for (int j = 0; j < 16; j++) {
                float other = __shfl_xor_sync(0xffffffffu, rv[j], 2);
                if ((t & 2) == 0) {
                    unsigned hh, ll;
                    split2(rv[j], other, hh, ll);
                    VTh[half*16 + j][kp] = hh;
                    VTl[half*16 + j][kp] = ll;
                }
            }
        }
        __syncthreads();

        // ---- scores S = Q K^T (bf16x3) ----
        float s[8][4];
        #pragma unroll
        for (int nt = 0; nt < 8; nt++)
            #pragma unroll
            for (int j = 0; j < 4; j++) s[nt][j] = 0.f;

        #pragma unroll
        for (int kc = 0; kc < 2; kc++) {
            const int kq = kc * 8 + tg;
            #pragma unroll
            for (int nt = 0; nt < 8; nt++) {
                const int nn = nt * 8 + g;
                const unsigned kh0 = Kh[nn][kq], kh1 = Kh[nn][kq+4];
                const unsigned kl0 = Kl[nn][kq], kl1 = Kl[nn][kq+4];
                mma_bf16(s[nt], ql[kc], kh0, kh1);
                mma_bf16(s[nt], qh[kc], kl0, kl1);
                mma_bf16(s[nt], qh[kc], kh0, kh1);
            }
        }

        // ---- key-tail masking ----
        if (k0 + 64 > CQ) {
            #pragma unroll
            for (int nt = 0; nt < 8; nt++) {
                const int kk = k0 + nt * 8 + 2 * tg;
                if (kk     >= CQ) { s[nt][0] = -1e30f; s[nt][2] = -1e30f; }
                if (kk + 1 >= CQ) { s[nt][1] = -1e30f; s[nt][3] = -1e30f; }
            }
        }

        // ---- online softmax (rows g and g+8) ----
        float cm0 = -1e30f, cm1 = -1e30f;
        #pragma unroll
        for (int nt = 0; nt < 8; nt++) {
            cm0 = fmaxf(cm0, fmaxf(s[nt][0], s[nt][1]));
            cm1 = fmaxf(cm1, fmaxf(s[nt][2], s[nt][3]));
        }
        cm0 = fmaxf(cm0, __shfl_xor_sync(0xffffffffu, cm0, 1));
        cm0 = fmaxf(cm0, __shfl_xor_sync(0xffffffffu, cm0, 2));
        cm1 = fmaxf(cm1, __shfl_xor_sync(0xffffffffu, cm1, 1));
        cm1 = fmaxf(cm1, __shfl_xor_sync(0xffffffffu, cm1, 2));

        const float nm0 = fmaxf(m0r, cm0), nm1 = fmaxf(m1r, cm1);
        const float f0 = __expf(m0r - nm0), f1 = __expf(m1r - nm1);
        m0r = nm0; m1r = nm1;
        #pragma unroll
        for (int nt = 0; nt < 4; nt++) {
            o[nt][0] *= f0; o[nt][1] *= f0;
            o[nt][2] *= f1; o[nt][3] *= f1;
        }

        float ps0 = 0.f, ps1 = 0.f;
        #pragma unroll
        for (int kc = 0; kc < 4; kc++) {
            // P fragments for key chunk kc from score frags 2kc, 2kc+1
            unsigned ph[4], pl[4];
            #pragma unroll
            for (int e = 0; e < 2; e++) {
                const int nt = 2*kc + e;
                const float p0 = __expf(s[nt][0] - nm0);
                const float p1 = __expf(s[nt][1] - nm0);
                const float p2 = __expf(s[nt][2] - nm1);
                const float p3 = __expf(s[nt][3] - nm1);
                ps0 += p0 + p1; ps1 += p2 + p3;
                unsigned hh0, ll0, hh1, ll1;
                split2(p0, p1, hh0, ll0);
                split2(p2, p3, hh1, ll1);
                ph[2*e]   = hh0; pl[2*e]   = ll0;   // rows g   (a0/a2)
                ph[2*e+1] = hh1; pl[2*e+1] = ll1;   // rows g+8 (a1/a3)
            }
            const int kq = kc * 8 + tg;
            #pragma unroll
            for (int ntd = 0; ntd < 4; ntd++) {
                const int nn = ntd * 8 + g;
                const unsigned vh0 = VTh[nn][kq], vh1 = VTh[nn][kq+4];
                const unsigned vl0 = VTl[nn][kq], vl1 = VTl[nn][kq+4];
                mma_bf16(o[ntd], pl, vh0, vh1);
                mma_bf16(o[ntd], ph, vl0, vl1);
                mma_bf16(o[ntd], ph, vh0, vh1);
            }
        }
        ps0 += __shfl_xor_sync(0xffffffffu, ps0, 1);
        ps0 += __shfl_xor_sync(0xffffffffu, ps0, 2);
        ps1 += __shfl_xor_sync(0xffffffffu, ps1, 1);
        ps1 += __shfl_xor_sync(0xffffffffu, ps1, 2);
        l0r = l0r * f0 + ps0;
        l1r = l1r * f1 + ps1;
    }

    // ---- epilogue ----
    const float inv0 = 1.f / l0r, inv1 = 1.f / l1r;
    const int gq0 = q0 + m0 + g, gq1 = gq0 + 8;
    #pragma unroll
    for (int nt = 0; nt < 4; nt++) {
        const int d = h * CDH + nt * 8 + 2 * tg;
        if (gq0 < CQ)
            *(float2*)&out[(basebq + gq0) * CD + d] = make_float2(o[nt][0]*inv0, o[nt][1]*inv0);
        if (gq1 < CQ)
            *(float2*)&out[(basebq + gq1) * CD + d] = make_float2(o[nt][2]*inv1, o[nt][3]*inv1);
    }
}

// ------------------------- fused residual-add + LayerNorm (+ optional qpos-add) -------------------------
__global__ void add_ln_kernel(const float* __restrict__ a, const float* __restrict__ r,
                              const float* __restrict__ g, const float* __restrict__ be,
                              float* __restrict__ out, float* __restrict__ out2,
                              const float* __restrict__ qpos, float* __restrict__ xpq) {
    int row = blockIdx.x, t = threadIdx.x;   // 256 threads, D=256
    size_t idx = (size_t)row * CD + t;
    float v = a[idx] + r[idx];

    __shared__ float red[8];
    __shared__ float stat[2];

    float s = v;
    #pragma unroll
    for (int o = 16; o > 0; o >>= 1) s += __shfl_xor_sync(0xffffffffu, s, o);
    if ((t & 31) == 0) red[t >> 5] = s;
    __syncthreads();
    if (t == 0) {
        float tot = 0.f;
        #pragma unroll
        for (int i = 0; i < 8; i++) tot += red[i];
        stat[0] = tot * (1.f / CD);
    }
    __syncthreads();
    float mu = stat[0];
    float d = v - mu;
    float s2 = d * d;
    #pragma unroll
    for (int o = 16; o > 0; o >>= 1) s2 += __shfl_xor_sync(0xffffffffu, s2, o);
    if ((t & 31) == 0) red[t >> 5] = s2;
    __syncthreads();
    if (t == 0) {
        float tot = 0.f;
        #pragma unroll
        for (int i = 0; i < 8; i++) tot += red[i];
        stat[1] = tot * (1.f / CD);
    }
    __syncthreads();
    float o = d * rsqrtf(stat[1] + 1e-5f) * g[t] + be[t];
    out[idx] = o;
    if (out2) out2[idx] = o;
    if (qpos) xpq[idx] = o + qpos[idx];
}

// ------------------------- MSDA gather: one block per (b,q), warp = head -------------------------
__global__ void msda_kernel(const float* __restrict__ value, const float* __restrict__ offaw,
                            const float* __restrict__ refp,
                            const float* __restrict__ vr, float* __restrict__ out) {
    int bq = blockIdx.x;
    int b = bq / CQ;
    int t = threadIdx.x;          // 256 threads = 8 warps
    int h = t >> 5, lane = t & 31;

    float logit = (lane < 16) ? offaw[(size_t)bq * 384 + 256 + h * 16 + lane] : -1e30f;
    float m = logit;
    #pragma unroll
    for (int o = 8; o > 0; o >>= 1) m = fmaxf(m, __shfl_xor_sync(0xffffffffu, m, o, 16));
    float e = (lane < 16) ? __expf(logit - m) : 0.f;
    float es = e;
    #pragma unroll
    for (int o = 8; o > 0; o >>= 1) es += __shfl_xor_sync(0xffffffffu, es, o, 16);
    float p = e / es;

    float rx = refp[(size_t)bq * 2 + 0];
    float ry = refp[(size_t)bq * 2 + 1];

    const int   Ws[4] = {100, 50, 25, 13};
    const int   Hs[4] = {100, 50, 25, 13};
    const int   ST[4] = {0, 10000, 12500, 13125};

    const float* voff = value + (size_t)b * CS * CD + h * CDH + lane;
    float acc = 0.f;

    #pragma unroll
    for (int l = 0; l < 4; l++) {
        int W_ = Ws[l], H_ = Hs[l], st = ST[l];
        float vrx = vr[b * 8 + l * 2 + 0];
        float vry = vr[b * 8 + l * 2 + 1];
        float bx = rx * vrx * (float)W_ - 0.5f;
        float by = ry * vry * (float)H_ - 0.5f;
        #pragma unroll
        for (int pp = 0; pp < 4; pp++) {
            size_t oidx = (size_t)bq * 384 + (size_t)(((h * 4 + l) * 4 + pp) * 2);
            float x = bx + offaw[oidx + 0];
            float y = by + offaw[oidx + 1];
            float w = __shfl_sync(0xffffffffu, p, l * 4 + pp, 32);
            float x0f = floorf(x), y0f = floorf(y);
            float wx = x - x0f, wy = y - y0f;
            int x0 = (int)x0f, y0 = (int)y0f;

            float gsum = 0.f;
            {
                int xi = x0, yi = y0;
                if (xi >= 0 && xi < W_ && yi >= 0 && yi < H_)
                    gsum = fmaf(voff[(size_t)(st + yi * W_ + xi) * CD], (1.f - wx) * (1.f - wy), gsum);
            }
            {
                int xi = x0 + 1, yi = y0;
                if (xi >= 0 && xi < W_ && yi >= 0 && yi < H_)
                    gsum = fmaf(voff[(size_t)(st + yi * W_ + xi) * CD], wx * (1.f - wy), gsum);
            }
            {
                int xi = x0, yi = y0 + 1;
                if (xi >= 0 && xi < W_ && yi >= 0 && yi < H_)
                    gsum = fmaf(voff[(size_t)(st + yi * W_ + xi) * CD], (1.f - wx) * wy, gsum);
            }
            {
                int xi = x0 + 1, yi = y0 + 1;
                if (xi >= 0 && xi < W_ && yi >= 0 && yi < H_)
                    gsum = fmaf(voff[(size_t)(st + yi * W_ + xi) * CD], wx * wy, gsum);
            }
            acc = fmaf(w, gsum, acc);
        }
    }
    out[(size_t)bq * CD + h * CDH + lane] = acc;
}

// ------------------------- inter_refs: reference_points repeated 6x -------------------------
__global__ void write_refs_kernel(const float* __restrict__ refp, float* __restrict__ out) {
    int i = blockIdx.x * blockDim.x + threadIdx.x;
    const int n = CB * CQ * 2;
    if (i < n) {
        float v = refp[i];
        #pragma unroll
        for (int L = 0; L < CNLAYERS; L++) out[(size_t)L * n + i] = v;
    }
}

// ------------------------- driver -------------------------
extern "C" void kernel_launch(void* const* d_in, const int* in_sizes, int n_in,
                              void* d_out, int out_size) {
    const float* tgt      = (const float*)d_in[0];
    const float* refp     = (const float*)d_in[1];
    const float* memory   = (const float*)d_in[2];
    const float* vratios  = (const float*)d_in[5];
    const float* qpos     = (const float*)d_in[6];
    const float* sa_in_w  = (const float*)d_in[7];
    const float* sa_in_b  = (const float*)d_in[8];
    const float* sa_out_w = (const float*)d_in[9];
    const float* sa_out_b = (const float*)d_in[10];
    const float* n1_g     = (const float*)d_in[11];
    const float* n1_b     = (const float*)d_in[12];
    const float* n2_g     = (const float*)d_in[13];
    const float* n2_b     = (const float*)d_in[14];
    const float* n3_g     = (const float*)d_in[15];
    const float* n3_b     = (const float*)d_in[16];
    const float* vp_w     = (const float*)d_in[17];
    const float* vp_b     = (const float*)d_in[18];
    const float* so_w     = (const float*)d_in[19];
    const float* so_b     = (const float*)d_in[20];
    const float* aw_w     = (const float*)d_in[21];
    const float* aw_b     = (const float*)d_in[22];
    const float* op_w     = (const float*)d_in[23];
    const float* op_b     = (const float*)d_in[24];
    const float* ff1_w    = (const float*)d_in[25];
    const float* ff1_b    = (const float*)d_in[26];
    const float* ff2_w    = (const float*)d_in[27];
    const float* ff2_b    = (const float*)d_in[28];

    float *value, *x, *xpq, *qkv, *attn, *t2, *offaw, *ms, *ffh, *sob;
    unsigned *wh, *wl;
    cudaGetSymbolAddress((void**)&value, g_value);
    cudaGetSymbolAddress((void**)&x,     g_x);
    cudaGetSymbolAddress((void**)&xpq,   g_xpq);
    cudaGetSymbolAddress((void**)&qkv,   g_qkv);
    cudaGetSymbolAddress((void**)&attn,  g_attn);
    cudaGetSymbolAddress((void**)&t2,    g_t2);
    cudaGetSymbolAddress((void**)&offaw, g_offaw);
    cudaGetSymbolAddress((void**)&ms,    g_ms);
    cudaGetSymbolAddress((void**)&ffh,   g_ffh);
    cudaGetSymbolAddress((void**)&sob,   g_sob);
    cudaGetSymbolAddress((void**)&wh,    g_wh);
    cudaGetSymbolAddress((void**)&wl,    g_wl);

    float* out = (float*)d_out;

    cudaMemcpyAsync(x, tgt, sizeof(float) * CBQ * CD, cudaMemcpyDeviceToDevice, 0);

    // split all weights into bf16 hi/lo planes (weights shared across layers)
    #define SPLITW(ptr, offp, npairs) \
        split_w_kernel<<<((npairs) + 255)/256, 256>>>(ptr, wh + (offp), wl + (offp), npairs)
    SPLITW(vp_w,     OFF_VP,   32768);
    SPLITW(sa_in_w,  OFF_SAIN, 98304);
    SPLITW(sa_out_w, OFF_SAOU, 32768);
    SPLITW(so_w,     OFF_SO,   32768);
    SPLITW(aw_w,     OFF_AW,   16384);   // contiguous after so -> combined [384,256]
    SPLITW(op_w,     OFF_OP,   32768);
    SPLITW(ff1_w,    OFF_FF1,  131072);
    SPLITW(ff2_w,    OFF_FF2,  131072);
    concat_bias_kernel<<<2, 256>>>(so_b, aw_b, sob);

    // layer-invariant value projection (computed ONCE)
    gemm_bf3<false><<<dim3(CD/128, (CBS + 127)/128), 256>>>(
        memory, wh + OFF_VP, wl + OFF_VP, vp_b, value, CBS, CD, CD);

    write_refs_kernel<<<(CB*CQ*2 + 255)/256, 256>>>(refp, out + (size_t)CNLAYERS * CBQ * CD);

    // initial xpq = tgt + query_pos
    add_kernel<<<(CBQ*CD + 255)/256, 256>>>(x, qpos, xpq, CBQ*CD);

    const int MB = (CBQ + 127) / 128;   // 57 row-blocks

    for (int L = 0; L < CNLAYERS; L++) {
        // ---- MHA ----
        gemm_bf3<false><<<dim3(768/128, MB), 256>>>(
            xpq, wh + OFF_SAIN, wl + OFF_SAIN, sa_in_b, qkv, CBQ, 3*CD, CD);
        flash_attn_tc<<<dim3(15, CNH, CB), 128>>>(qkv, attn);
        gemm_bf3<false><<<dim3(CD/128, MB), 256>>>(
            attn, wh + OFF_SAOU, wl + OFF_SAOU, sa_out_b, t2, CBQ, CD, CD);
        add_ln_kernel<<<CBQ, CD>>>(xpq, t2, n1_g, n1_b, x, nullptr, nullptr, nullptr);

        // ---- MSDA ----
        gemm_bf3<false><<<dim3(384/128, MB), 256>>>(
            x, wh + OFF_SO, wl + OFF_SO, sob, offaw, CBQ, 384, CD);
        msda_kernel<<<CBQ, 256>>>(value, offaw, refp, vratios, ms);
        gemm_bf3<false><<<dim3(CD/128, MB), 256>>>(
            ms, wh + OFF_OP, wl + OFF_OP, op_b, t2, CBQ, CD, CD);
        add_ln_kernel<<<CBQ, CD>>>(x, t2, n2_g, n2_b, x, nullptr, nullptr, nullptr);

        // ---- FFN ----
        gemm_bf3<true ><<<dim3(CFF/128, MB), 256>>>(
            x, wh + OFF_FF1, wl + OFF_FF1, ff1_b, ffh, CBQ, CFF, CD);
        gemm_bf3<false><<<dim3(CD/128, MB), 256>>>(
            ffh, wh + OFF_FF2, wl + OFF_FF2, ff2_b, t2, CBQ, CD, CFF);
        // fused: x = LN(x + t2); out[L] = x; xpq = x + qpos (for next layer)
        add_ln_kernel<<<CBQ, CD>>>(x, t2, n3_g, n3_b, x, out + (size_t)L * CBQ * CD, qpos, xpq);
    }
}